// round 7
// baseline (speedup 1.0000x reference)
#include <cuda_runtime.h>
#include <math.h>

#define Bx 8
#define Nx 512
#define Dx 128
#define Hx 64
#define FNx 3
#define NLx 3
#define OUTC 10
#define BN (Bx*Nx)

// ---------------- device scratch (static, no allocation) ----------------
__device__ float    g_kap[BN];
__device__ float    g_f[FNx][BN];
__device__ float    g_m1;
__device__ unsigned g_adj[BN*16];       // 512-bit row bitmask per node
__device__ unsigned g_kmask1[Bx*16];    // keep bitmask after prune 1
__device__ unsigned g_kmask2[Bx*16];    // cumulative keep after prune 2
__device__ float    g_batchloss[Bx];
__device__ float    g_h[NLx][BN*Hx];
__device__ float    g_part[Bx*8*320];

// ---------------- kernel 1: compress binary A to bitmasks ----------------
// grid 512 blocks x 256 threads; warp per row
__global__ void adjmask_kernel(const float* __restrict__ A)
{
    int w = threadIdx.x >> 5, lane = threadIdx.x & 31;
    int r = blockIdx.x * 8 + w;
    const float* Ar = A + (size_t)r * Nx;
    unsigned myword = 0;
    #pragma unroll
    for (int c = 0; c < 16; c++) {
        float v = Ar[c*32 + lane];
        unsigned m = __ballot_sync(0xffffffffu, v != 0.f);
        if (lane == c) myword = m;
    }
    if (lane < 16) g_adj[(size_t)r*16 + lane] = myword;
}

// ---------------- kernel 2: node MLPs (curv + 3 fn), tiled; m1 as slice 4 --
// grid (BN/32, 5), 256 threads, dynamic smem 57600 B
__global__ void node_mlps_tiled(const float* __restrict__ X,
    const float* __restrict__ cW1, const float* __restrict__ cb1,
    const float* __restrict__ cW2, const float* __restrict__ cb2,
    const float* __restrict__ fW1, const float* __restrict__ fb1,
    const float* __restrict__ fW2, const float* __restrict__ fb2,
    const float* __restrict__ wmW1, const float* __restrict__ wmb1,
    const float* __restrict__ wmW2, const float* __restrict__ wmb2,
    const float* __restrict__ wmW3, const float* __restrict__ wmb3)
{
    extern __shared__ float sm[];
    int tid = threadIdx.x;
    int m = blockIdx.y;

    if (m == 4) {   // scalar m1 = sigmoid(MLP(1)) — only block 0 of this slice
        if (blockIdx.x != 0) return;
        float* s1 = sm;        // 64
        float* s2 = sm + 64;   // 32
        if (tid < 64) s1[tid] = fmaxf(wmW1[tid] + wmb1[tid], 0.f);
        __syncthreads();
        if (tid < 32) {
            float a = wmb2[tid];
            #pragma unroll
            for (int i = 0; i < 64; i++) a += s1[i] * wmW2[i*32 + tid];
            s2[tid] = fmaxf(a, 0.f);
        }
        __syncthreads();
        if (tid == 0) {
            float s = wmb3[0];
            #pragma unroll
            for (int i = 0; i < 32; i++) s += s2[i] * wmW3[i];
            g_m1 = 1.f / (1.f + expf(-s));
        }
        return;
    }

    float* sX   = sm;                    // 32*128 = 4096
    float* sW1  = sm + 4096;             // 128*64 = 8192
    float* sHid = sm + 4096 + 8192;      // 32*64  = 2048
    float* sW2v = sHid + 2048;           // 64
    int nodeBase = blockIdx.x * 32;

    const float* W1 = (m == 0) ? cW1 : fW1 + (size_t)(m-1)*Dx*Hx;
    const float* B1 = (m == 0) ? cb1 : fb1 + (m-1)*Hx;
    const float* W2 = (m == 0) ? cW2 : fW2 + (m-1)*Hx;
    float B2 = (m == 0) ? cb2[0] : fb2[m-1];

    for (int i = tid; i < 32*Dx; i += 256) sX[i] = X[(size_t)nodeBase*Dx + i];
    for (int i = tid; i < Dx*Hx; i += 256) sW1[i] = W1[i];
    if (tid < 64) sW2v[tid] = W2[tid];
    __syncthreads();

    // hidden: thread owns 2 h-cols x 4 nodes
    {
        int h2 = tid & 31, g8 = tid >> 5;
        float r[4][2];
        float b1a = B1[2*h2], b1b = B1[2*h2+1];
        #pragma unroll
        for (int k = 0; k < 4; k++) { r[k][0] = b1a; r[k][1] = b1b; }
        for (int d = 0; d < Dx; d++) {
            float2 wv = *(const float2*)&sW1[d*64 + 2*h2];
            #pragma unroll
            for (int k = 0; k < 4; k++) {
                float a = sX[(g8 + 8*k)*Dx + d];
                r[k][0] += a * wv.x; r[k][1] += a * wv.y;
            }
        }
        #pragma unroll
        for (int k = 0; k < 4; k++) {
            float2 o; o.x = fmaxf(r[k][0], 0.f); o.y = fmaxf(r[k][1], 0.f);
            *(float2*)&sHid[(g8 + 8*k)*64 + 2*h2] = o;
        }
    }
    __syncthreads();

    // scalar head: warp per node (4 rounds)
    int w = tid >> 5, lane = tid & 31;
    for (int nn = 0; nn < 4; nn++) {
        int nl = w*4 + nn;
        float v = sHid[nl*64 + lane] * sW2v[lane]
                + sHid[nl*64 + 32 + lane] * sW2v[32 + lane];
        #pragma unroll
        for (int o = 16; o > 0; o >>= 1) v += __shfl_xor_sync(0xffffffffu, v, o);
        if (lane == 0) {
            float s = v + B2;
            float sig = 1.f / (1.f + expf(-s));
            int node = nodeBase + nl;
            if (m == 0) g_kap[node] = sig; else g_f[m-1][node] = sig;
        }
    }
}

// ---------------- kernel 3: top-k prune -> keep bitmasks (exact jax ties) --
// grid = B blocks, 512 threads
__global__ void prune_kernel(const int* __restrict__ p_ptr)
{
    __shared__ float sv[Nx];
    __shared__ float so[Nx];
    int b = blockIdx.x, t = threadIdx.x;
    float v = g_kap[b*Nx + t];
    so[t] = v; sv[t] = v;
    __syncthreads();
    for (int k = 2; k <= Nx; k <<= 1) {
      for (int j = k >> 1; j > 0; j >>= 1) {
        int ixj = t ^ j;
        if (ixj > t) {
          float a = sv[t], c = sv[ixj];
          bool up = ((t & k) == 0);
          if ((a > c) == up) { sv[t] = c; sv[ixj] = a; }
        }
        __syncthreads();
      }
    }
    int p = *p_ptr;
    float keepA = 1.f, keepB = 1.f;
    for (int phase = 0; phase < 2; phase++) {
        int k = (Nx * p * (phase+1)) / 100;
        bool removed = false;
        if (k >= 1) {
            float T = sv[Nx - k];
            int isgt = (so[t] > T) ? 1 : 0;
            int cgt = __syncthreads_count(isgt);
            int need = k - cgt;
            removed = (so[t] > T);
            if (!removed && so[t] == T && need > 0) {
                int r = 0;
                for (int j = 0; j < t; j++) if (so[j] == T) r++;
                if (r < need) removed = true;
            }
        }
        if (phase == 0) keepA = removed ? 0.f : 1.f; else keepB = removed ? 0.f : 1.f;
        __syncthreads();
    }
    unsigned m1b = __ballot_sync(0xffffffffu, keepA != 0.f);
    unsigned m2b = __ballot_sync(0xffffffffu, keepA * keepB != 0.f);
    if ((t & 31) == 0) {
        g_kmask1[b*16 + (t >> 5)] = m1b;
        g_kmask2[b*16 + (t >> 5)] = m2b;
    }
}

// ---------------- kernel 4: fused curvature (both passes + loss per batch) -
// grid = Bx blocks, 512 threads (thread per row)
__global__ void curv_kernel()
{
    __shared__ float  sf[FNx][Nx];
    __shared__ float4 sg[FNx][Nx];   // (gamma, df, f*df, -)
    __shared__ float  red[Nx];
    int b = blockIdx.x, t = threadIdx.x;
    int idx = b*Nx + t;
    #pragma unroll
    for (int i = 0; i < FNx; i++) sf[i][t] = g_f[i][idx];
    unsigned wrd[16];
    #pragma unroll
    for (int c = 0; c < 16; c++) wrd[c] = g_adj[(size_t)idx*16 + c];
    __syncthreads();

    float m1 = g_m1;
    int degi = 0;
    #pragma unroll
    for (int c = 0; c < 16; c++) degi += __popc(wrd[c]);
    float deg = (float)degi;

    float u1[FNx] = {0,0,0}, u2[FNx] = {0,0,0};
    #pragma unroll
    for (int c = 0; c < 16; c++) {
        unsigned bits = wrd[c];
        while (bits) {
            int j = c*32 + __ffs(bits) - 1; bits &= bits - 1;
            #pragma unroll
            for (int i = 0; i < FNx; i++) { float fv = sf[i][j]; u1[i] += fv; u2[i] += fv*fv; }
        }
    }
    #pragma unroll
    for (int i = 0; i < FNx; i++) {
        float fr = sf[i][t];
        float gam = 0.5f*m1*(fr*fr*deg - 2.f*fr*u1[i] + u2[i]);
        float df  = m1*(fr*deg - u1[i]);
        sg[i][t] = make_float4(gam, df, fr*df, 0.f);
    }
    __syncthreads();

    float v1[FNx] = {0,0,0}, v2[FNx] = {0,0,0}, v3[FNx] = {0,0,0};
    #pragma unroll
    for (int c = 0; c < 16; c++) {
        unsigned bits = wrd[c];
        while (bits) {
            int j = c*32 + __ffs(bits) - 1; bits &= bits - 1;
            #pragma unroll
            for (int i = 0; i < FNx; i++) {
                float4 g = sg[i][j];
                v1[i] += g.x; v2[i] += g.y; v3[i] += g.z;
            }
        }
    }
    float kap = g_kap[idx], term = 0.f;
    #pragma unroll
    for (int i = 0; i < FNx; i++) {
        float4 own = sg[i][t]; float fr = sf[i][t];
        float dgam = m1*(own.x*deg - v1[i]);
        float gfd  = 0.5f*m1*(own.z*deg - fr*v2[i] - own.y*u1[i] + v3[i]);
        float g2 = 0.5f*dgam - gfd;
        term += fmaxf(kap*own.x - g2, 0.f);
    }
    red[t] = term - 3.f*kap;
    __syncthreads();
    for (int o = 256; o > 0; o >>= 1) { if (t < o) red[t] += red[t + o]; __syncthreads(); }
    if (t == 0) g_batchloss[b] = red[0];
}

// ---------------- kernel 5: fused sparse-aggregation + GIN 2-layer MLP -----
// grid = 128 blocks, 256 threads, dynamic smem
template<int DIN>
__global__ void gin_kernel(const float* __restrict__ hin,
    const unsigned* __restrict__ kmask,
    const float* __restrict__ eps_ptr, int t_idx,
    const float* __restrict__ W1, const float* __restrict__ b1,
    const float* __restrict__ W2, const float* __restrict__ b2,
    float* __restrict__ hout)
{
    extern __shared__ float sm2[];
    float* sW1  = sm2;                    // DIN*64
    float* sW2  = sW1 + DIN*64;           // 64*64
    float* sAgg = sW2 + 64*64;            // 32*DIN
    float* sHid = sAgg + 32*DIN;          // 32*64
    const int tid = threadIdx.x;
    const int nodeBase = blockIdx.x * 32;
    const int b = nodeBase >> 9;

    for (int i = tid; i < DIN*64; i += 256) sW1[i] = W1[i];
    for (int i = tid; i < 64*64; i += 256)  sW2[i] = W2[i];

    const int w = tid >> 5, lane = tid & 31;
    const float eps1 = 1.f + eps_ptr[t_idx];
    const unsigned full = 0xffffffffu;

    for (int nn = 0; nn < 4; nn++) {
        int nl = w*4 + nn;
        int node = nodeBase + nl;
        unsigned myw = 0;
        if (lane < 16) {
            myw = g_adj[(size_t)node*16 + lane];
            if (kmask) myw &= kmask[b*16 + lane];
        }
        bool rk = true;
        if (kmask) rk = (kmask[b*16 + ((node & 511) >> 5)] >> (node & 31)) & 1u;
        float acc[DIN/32];
        #pragma unroll
        for (int q = 0; q < DIN/32; q++) acc[q] = 0.f;
        if (rk) {
            #pragma unroll 1
            for (int c = 0; c < 16; c++) {
                unsigned bits = __shfl_sync(full, myw, c);
                while (bits) {
                    int j = __ffs(bits) - 1; bits &= bits - 1;
                    const float* hr = hin + ((size_t)(b*Nx + c*32 + j))*DIN;
                    #pragma unroll
                    for (int q = 0; q < DIN/32; q++) acc[q] += hr[lane + 32*q];
                }
            }
        }
        const float* hs = hin + (size_t)node*DIN;
        #pragma unroll
        for (int q = 0; q < DIN/32; q++)
            sAgg[nl*DIN + lane + 32*q] = eps1*hs[lane + 32*q] + acc[q];
    }
    __syncthreads();

    // hidden layer: thread owns 2 cols x 4 nodes
    {
        int h2 = tid & 31, g8 = tid >> 5;
        float r[4][2];
        float b1a = b1[2*h2], b1b = b1[2*h2+1];
        #pragma unroll
        for (int k = 0; k < 4; k++) { r[k][0] = b1a; r[k][1] = b1b; }
        for (int d = 0; d < DIN; d++) {
            float2 wv = *(const float2*)&sW1[d*64 + 2*h2];
            #pragma unroll
            for (int k = 0; k < 4; k++) {
                float a = sAgg[(g8 + 8*k)*DIN + d];
                r[k][0] += a * wv.x; r[k][1] += a * wv.y;
            }
        }
        #pragma unroll
        for (int k = 0; k < 4; k++) {
            float2 o; o.x = fmaxf(r[k][0], 0.f); o.y = fmaxf(r[k][1], 0.f);
            *(float2*)&sHid[(g8 + 8*k)*64 + 2*h2] = o;
        }
    }
    __syncthreads();

    // output layer
    {
        int h2 = tid & 31, g8 = tid >> 5;
        float r[4][2];
        float b2a = b2[2*h2], b2b = b2[2*h2+1];
        #pragma unroll
        for (int k = 0; k < 4; k++) { r[k][0] = b2a; r[k][1] = b2b; }
        for (int d = 0; d < 64; d++) {
            float2 wv = *(const float2*)&sW2[d*64 + 2*h2];
            #pragma unroll
            for (int k = 0; k < 4; k++) {
                float a = sHid[(g8 + 8*k)*64 + d];
                r[k][0] += a * wv.x; r[k][1] += a * wv.y;
            }
        }
        #pragma unroll
        for (int k = 0; k < 4; k++) {
            float2 o; o.x = fmaxf(r[k][0], 0.f); o.y = fmaxf(r[k][1], 0.f);
            *(float2*)&hout[((size_t)(nodeBase + g8 + 8*k))*64 + 2*h2] = o;
        }
    }
}

// ---------------- kernel 6: readout stage 1 (partial column sums) ----------
// grid (Bx, 8), 320 threads
__global__ void final_part_kernel(const float* __restrict__ X)
{
    int b = blockIdx.x, pp = blockIdx.y, t = threadIdx.x;
    int n0 = pp * 64;
    float a = 0.f;
    if (t < 128) {
        for (int n = n0; n < n0 + 64; n++) a += X[((size_t)(b*Nx + n))*Dx + t];
    } else {
        int layer = (t - 128) >> 6, c = (t - 128) & 63;
        const float* H = &g_h[layer][0];
        for (int n = n0; n < n0 + 64; n++) a += H[(b*Nx + n)*Hx + c];
    }
    g_part[(b*8 + pp)*320 + t] = a;
}

// ---------------- kernel 7: readout stage 2 (matmul + loss write) ----------
// grid = Bx, 320 threads
__global__ void final_out_kernel(const float* __restrict__ outW,
                                 const float* __restrict__ outb,
                                 float* __restrict__ dout, int out_size)
{
    __shared__ float S[320];
    int b = blockIdx.x, t = threadIdx.x;
    float a = 0.f;
    #pragma unroll
    for (int p2 = 0; p2 < 8; p2++) a += g_part[(b*8 + p2)*320 + t];
    S[t] = a;
    __syncthreads();
    if (t < OUTC) {
        float o = outb[t];
        for (int f = 0; f < 320; f++) o += S[f] * outW[f*OUTC + t];
        dout[b*OUTC + t] = o;
    }
    if (b == 0 && t == OUTC && out_size > Bx*OUTC) {
        float l = 0.f;
        #pragma unroll
        for (int i = 0; i < Bx; i++) l += g_batchloss[i];
        dout[Bx*OUTC] = l;
    }
}

// ---------------- launch ----------------
extern "C" void kernel_launch(void* const* d_in, const int* in_sizes, int n_in,
                              void* d_out, int out_size) {
    const float* X    = (const float*)d_in[0];
    const float* A    = (const float*)d_in[1];
    const int*   p    = (const int*)  d_in[2];
    const float* cW1  = (const float*)d_in[3];
    const float* cb1  = (const float*)d_in[4];
    const float* cW2  = (const float*)d_in[5];
    const float* cb2  = (const float*)d_in[6];
    const float* wmW1 = (const float*)d_in[7];
    const float* wmb1 = (const float*)d_in[8];
    const float* wmW2 = (const float*)d_in[9];
    const float* wmb2 = (const float*)d_in[10];
    const float* wmW3 = (const float*)d_in[11];
    const float* wmb3 = (const float*)d_in[12];
    const float* fW1  = (const float*)d_in[13];
    const float* fb1  = (const float*)d_in[14];
    const float* fW2  = (const float*)d_in[15];
    const float* fb2  = (const float*)d_in[16];
    const float* eps  = (const float*)d_in[17];
    const float* g0W1 = (const float*)d_in[18];
    const float* g0b1 = (const float*)d_in[19];
    const float* g0W2 = (const float*)d_in[20];
    const float* g0b2 = (const float*)d_in[21];
    const float* g1W1 = (const float*)d_in[22];
    const float* g1b1 = (const float*)d_in[23];
    const float* g1W2 = (const float*)d_in[24];
    const float* g1b2 = (const float*)d_in[25];
    const float* g2W1 = (const float*)d_in[26];
    const float* g2b1 = (const float*)d_in[27];
    const float* g2W2 = (const float*)d_in[28];
    const float* g2b2 = (const float*)d_in[29];
    const float* outW = (const float*)d_in[30];
    const float* outb = (const float*)d_in[31];
    float* dout = (float*)d_out;

    float *h0_p, *h1_p, *h2_p;
    unsigned *km1_p, *km2_p;
    cudaGetSymbolAddress((void**)&h0_p, g_h);
    h1_p = h0_p + BN*Hx;
    h2_p = h0_p + 2*BN*Hx;
    cudaGetSymbolAddress((void**)&km1_p, g_kmask1);
    cudaGetSymbolAddress((void**)&km2_p, g_kmask2);

    // dynamic smem limits (idempotent host-side calls)
    cudaFuncSetAttribute((const void*)node_mlps_tiled,
        cudaFuncAttributeMaxDynamicSharedMemorySize, 57600);
    cudaFuncSetAttribute((const void*)gin_kernel<128>,
        cudaFuncAttributeMaxDynamicSharedMemorySize, 73728);
    cudaFuncSetAttribute((const void*)gin_kernel<64>,
        cudaFuncAttributeMaxDynamicSharedMemorySize, 49152);

    adjmask_kernel<<<BN/8, 256>>>(A);
    node_mlps_tiled<<<dim3(BN/32, 5), 256, 57600>>>(X,
        cW1, cb1, cW2, cb2, fW1, fb1, fW2, fb2,
        wmW1, wmb1, wmW2, wmb2, wmW3, wmb3);
    prune_kernel<<<Bx, Nx>>>(p);
    curv_kernel<<<Bx, Nx>>>();

    gin_kernel<128><<<BN/32, 256, 73728>>>(X,    nullptr, eps, 0, g0W1, g0b1, g0W2, g0b2, h0_p);
    gin_kernel<64> <<<BN/32, 256, 49152>>>(h0_p, km1_p,   eps, 1, g1W1, g1b1, g1W2, g1b2, h1_p);
    gin_kernel<64> <<<BN/32, 256, 49152>>>(h1_p, km2_p,   eps, 2, g2W1, g2b1, g2W2, g2b2, h2_p);

    final_part_kernel<<<dim3(Bx, 8), 320>>>(X);
    final_out_kernel<<<Bx, 320>>>(outW, outb, dout, out_size);
}

// round 8
// speedup vs baseline: 1.1203x; 1.1203x over previous
#include <cuda_runtime.h>
#include <math.h>

#define Bx 8
#define Nx 512
#define Dx 128
#define Hx 64
#define FNx 3
#define NLx 3
#define OUTC 10
#define BN (Bx*Nx)
#define NBCAP 128

// ---------------- device scratch (static, no allocation) ----------------
__device__ float    g_kap[BN];
__device__ float    g_f[FNx][BN];
__device__ float    g_m1;
__device__ unsigned g_adj[BN*16];           // 512-bit row bitmask per node
__device__ unsigned short g_nbr[BN*NBCAP];  // CSR neighbor lists
__device__ int      g_ndeg[BN];
__device__ unsigned g_kmask1[Bx*16];
__device__ unsigned g_kmask2[Bx*16];
__device__ float    g_deg[BN];
__device__ float    g_u1[FNx][BN];
__device__ float    g_gamma[FNx][BN];
__device__ float    g_df[FNx][BN];
__device__ float    g_fdf[FNx][BN];
__device__ float    g_rowloss[BN];
__device__ float    g_h[NLx][BN*Hx];
__device__ float    g_part[Bx*8*320];

// ---------------- kernel 1: compress A to bitmasks + CSR lists ------------
// grid 512 blocks x 256 threads; warp per row
__global__ void adjmask_kernel(const float* __restrict__ A)
{
    const unsigned full = 0xffffffffu;
    int w = threadIdx.x >> 5, lane = threadIdx.x & 31;
    int r = blockIdx.x * 8 + w;
    const float* Ar = A + (size_t)r * Nx;
    unsigned myword = 0;
    #pragma unroll
    for (int c = 0; c < 16; c++) {
        float v = Ar[c*32 + lane];
        unsigned m = __ballot_sync(full, v != 0.f);
        if (lane == c) myword = m;
    }
    if (lane < 16) g_adj[(size_t)r*16 + lane] = myword;

    // CSR compaction via warp scan (words ascending -> sorted neighbor list)
    unsigned wv = (lane < 16) ? myword : 0u;
    int cnt = __popc(wv);
    int ex = cnt;
    #pragma unroll
    for (int o = 1; o < 32; o <<= 1) {
        int nv = __shfl_up_sync(full, ex, o);
        if (lane >= o) ex += nv;
    }
    int total = __shfl_sync(full, ex, 15);
    ex -= cnt;              // exclusive prefix
    if (lane < 16) {
        int pos = ex;
        unsigned bits = wv;
        while (bits) {
            int j = __ffs(bits) - 1; bits &= bits - 1;
            if (pos < NBCAP) g_nbr[(size_t)r*NBCAP + pos] = (unsigned short)(lane*32 + j);
            pos++;
        }
    }
    if (lane == 0) g_ndeg[r] = (total < NBCAP) ? total : NBCAP;
}

// ---------------- kernel 2: node MLPs (curv + 3 fn), tiled; m1 slice 4 ----
// grid (BN/32, 5), 256 threads, dynamic smem 57600 B
__global__ void node_mlps_tiled(const float* __restrict__ X,
    const float* __restrict__ cW1, const float* __restrict__ cb1,
    const float* __restrict__ cW2, const float* __restrict__ cb2,
    const float* __restrict__ fW1, const float* __restrict__ fb1,
    const float* __restrict__ fW2, const float* __restrict__ fb2,
    const float* __restrict__ wmW1, const float* __restrict__ wmb1,
    const float* __restrict__ wmW2, const float* __restrict__ wmb2,
    const float* __restrict__ wmW3, const float* __restrict__ wmb3)
{
    extern __shared__ float sm[];
    int tid = threadIdx.x;
    int m = blockIdx.y;

    if (m == 4) {
        if (blockIdx.x != 0) return;
        float* s1 = sm;
        float* s2 = sm + 64;
        if (tid < 64) s1[tid] = fmaxf(wmW1[tid] + wmb1[tid], 0.f);
        __syncthreads();
        if (tid < 32) {
            float a = wmb2[tid];
            #pragma unroll
            for (int i = 0; i < 64; i++) a += s1[i] * wmW2[i*32 + tid];
            s2[tid] = fmaxf(a, 0.f);
        }
        __syncthreads();
        if (tid == 0) {
            float s = wmb3[0];
            #pragma unroll
            for (int i = 0; i < 32; i++) s += s2[i] * wmW3[i];
            g_m1 = 1.f / (1.f + expf(-s));
        }
        return;
    }

    float* sX   = sm;                    // 32*128
    float* sW1  = sm + 4096;             // 128*64
    float* sHid = sm + 4096 + 8192;      // 32*64
    float* sW2v = sHid + 2048;           // 64
    int nodeBase = blockIdx.x * 32;

    const float* W1 = (m == 0) ? cW1 : fW1 + (size_t)(m-1)*Dx*Hx;
    const float* B1 = (m == 0) ? cb1 : fb1 + (m-1)*Hx;
    const float* W2 = (m == 0) ? cW2 : fW2 + (m-1)*Hx;
    float B2 = (m == 0) ? cb2[0] : fb2[m-1];

    for (int i = tid; i < 32*Dx; i += 256) sX[i] = X[(size_t)nodeBase*Dx + i];
    for (int i = tid; i < Dx*Hx; i += 256) sW1[i] = W1[i];
    if (tid < 64) sW2v[tid] = W2[tid];
    __syncthreads();

    {
        int h2 = tid & 31, g8 = tid >> 5;
        float r[4][2];
        float b1a = B1[2*h2], b1b = B1[2*h2+1];
        #pragma unroll
        for (int k = 0; k < 4; k++) { r[k][0] = b1a; r[k][1] = b1b; }
        for (int d = 0; d < Dx; d++) {
            float2 wv = *(const float2*)&sW1[d*64 + 2*h2];
            #pragma unroll
            for (int k = 0; k < 4; k++) {
                float a = sX[(g8 + 8*k)*Dx + d];
                r[k][0] += a * wv.x; r[k][1] += a * wv.y;
            }
        }
        #pragma unroll
        for (int k = 0; k < 4; k++) {
            float2 o; o.x = fmaxf(r[k][0], 0.f); o.y = fmaxf(r[k][1], 0.f);
            *(float2*)&sHid[(g8 + 8*k)*64 + 2*h2] = o;
        }
    }
    __syncthreads();

    int w = tid >> 5, lane = tid & 31;
    for (int nn = 0; nn < 4; nn++) {
        int nl = w*4 + nn;
        float v = sHid[nl*64 + lane] * sW2v[lane]
                + sHid[nl*64 + 32 + lane] * sW2v[32 + lane];
        #pragma unroll
        for (int o = 16; o > 0; o >>= 1) v += __shfl_xor_sync(0xffffffffu, v, o);
        if (lane == 0) {
            float sig = 1.f / (1.f + expf(-(v + B2)));
            int node = nodeBase + nl;
            if (m == 0) g_kap[node] = sig; else g_f[m-1][node] = sig;
        }
    }
}

// ---------------- kernel 3: top-k prune -> keep bitmasks ------------------
__global__ void prune_kernel(const int* __restrict__ p_ptr)
{
    __shared__ float sv[Nx];
    __shared__ float so[Nx];
    int b = blockIdx.x, t = threadIdx.x;
    float v = g_kap[b*Nx + t];
    so[t] = v; sv[t] = v;
    __syncthreads();
    for (int k = 2; k <= Nx; k <<= 1) {
      for (int j = k >> 1; j > 0; j >>= 1) {
        int ixj = t ^ j;
        if (ixj > t) {
          float a = sv[t], c = sv[ixj];
          bool up = ((t & k) == 0);
          if ((a > c) == up) { sv[t] = c; sv[ixj] = a; }
        }
        __syncthreads();
      }
    }
    int p = *p_ptr;
    float keepA = 1.f, keepB = 1.f;
    for (int phase = 0; phase < 2; phase++) {
        int k = (Nx * p * (phase+1)) / 100;
        bool removed = false;
        if (k >= 1) {
            float T = sv[Nx - k];
            int isgt = (so[t] > T) ? 1 : 0;
            int cgt = __syncthreads_count(isgt);
            int need = k - cgt;
            removed = (so[t] > T);
            if (!removed && so[t] == T && need > 0) {
                int r = 0;
                for (int j = 0; j < t; j++) if (so[j] == T) r++;
                if (r < need) removed = true;
            }
        }
        if (phase == 0) keepA = removed ? 0.f : 1.f; else keepB = removed ? 0.f : 1.f;
        __syncthreads();
    }
    unsigned m1b = __ballot_sync(0xffffffffu, keepA != 0.f);
    unsigned m2b = __ballot_sync(0xffffffffu, keepA * keepB != 0.f);
    if ((t & 31) == 0) {
        g_kmask1[b*16 + (t >> 5)] = m1b;
        g_kmask2[b*16 + (t >> 5)] = m2b;
    }
}

// ---------------- kernel 4: curvature pass 1 (bitmask, warp per row) ------
// grid (64, Bx), 256 threads
__global__ void curv1_kernel()
{
    __shared__ float sf[FNx][Nx];
    const unsigned full = 0xffffffffu;
    int b = blockIdx.y, tid = threadIdx.x;
    for (int i = tid; i < FNx*Nx; i += 256)
        sf[i >> 9][i & 511] = g_f[i >> 9][b*Nx + (i & 511)];
    __syncthreads();

    int w = tid >> 5, lane = tid & 31;
    int row = blockIdx.x*8 + w;
    int idx = b*Nx + row;
    unsigned myw = (lane < 16) ? g_adj[(size_t)idx*16 + lane] : 0u;
    int degi = __popc(myw);
    float u1[FNx] = {0,0,0}, u2[FNx] = {0,0,0};
    #pragma unroll
    for (int c = 0; c < 16; c++) {
        unsigned bits = __shfl_sync(full, myw, c);
        float sel = (float)((bits >> lane) & 1u);
        #pragma unroll
        for (int i = 0; i < FNx; i++) {
            float fv = sf[i][c*32 + lane];
            u1[i] += sel * fv;
            u2[i] += sel * fv * fv;
        }
    }
    #pragma unroll
    for (int o = 16; o > 0; o >>= 1) {
        degi += __shfl_xor_sync(full, degi, o);
        #pragma unroll
        for (int i = 0; i < FNx; i++) {
            u1[i] += __shfl_xor_sync(full, u1[i], o);
            u2[i] += __shfl_xor_sync(full, u2[i], o);
        }
    }
    if (lane == 0) {
        float m1 = g_m1;
        float deg = (float)degi;
        g_deg[idx] = deg;
        #pragma unroll
        for (int i = 0; i < FNx; i++) {
            float fr = sf[i][row];
            g_u1[i][idx] = u1[i];
            float gam = 0.5f*m1*(fr*fr*deg - 2.f*fr*u1[i] + u2[i]);
            float df  = m1*(fr*deg - u1[i]);
            g_gamma[i][idx] = gam; g_df[i][idx] = df; g_fdf[i][idx] = fr*df;
        }
    }
}

// ---------------- kernel 5: curvature pass 2 (bitmask, warp per row) ------
// grid (64, Bx), 256 threads
__global__ void curv2_kernel()
{
    __shared__ float sgam[FNx][Nx], sdf[FNx][Nx], sfd[FNx][Nx];
    const unsigned full = 0xffffffffu;
    int b = blockIdx.y, tid = threadIdx.x;
    for (int i = tid; i < FNx*Nx; i += 256) {
        int f = i >> 9, j = i & 511, id2 = b*Nx + j;
        sgam[f][j] = g_gamma[f][id2];
        sdf[f][j]  = g_df[f][id2];
        sfd[f][j]  = g_fdf[f][id2];
    }
    __syncthreads();

    int w = tid >> 5, lane = tid & 31;
    int row = blockIdx.x*8 + w;
    int idx = b*Nx + row;
    unsigned myw = (lane < 16) ? g_adj[(size_t)idx*16 + lane] : 0u;
    float v1[FNx] = {0,0,0}, v2[FNx] = {0,0,0}, v3[FNx] = {0,0,0};
    #pragma unroll
    for (int c = 0; c < 16; c++) {
        unsigned bits = __shfl_sync(full, myw, c);
        float sel = (float)((bits >> lane) & 1u);
        #pragma unroll
        for (int i = 0; i < FNx; i++) {
            int j = c*32 + lane;
            v1[i] += sel * sgam[i][j];
            v2[i] += sel * sdf[i][j];
            v3[i] += sel * sfd[i][j];
        }
    }
    #pragma unroll
    for (int o = 16; o > 0; o >>= 1) {
        #pragma unroll
        for (int i = 0; i < FNx; i++) {
            v1[i] += __shfl_xor_sync(full, v1[i], o);
            v2[i] += __shfl_xor_sync(full, v2[i], o);
            v3[i] += __shfl_xor_sync(full, v3[i], o);
        }
    }
    if (lane == 0) {
        float m1 = g_m1, deg = g_deg[idx], kap = g_kap[idx];
        float term = 0.f;
        #pragma unroll
        for (int i = 0; i < FNx; i++) {
            float gam = sgam[i][row], df = sdf[i][row], fdf = sfd[i][row];
            float fr = g_f[i][idx];
            float u1 = g_u1[i][idx];
            float dgam = m1*(gam*deg - v1[i]);
            float gfd  = 0.5f*m1*(fdf*deg - fr*v2[i] - df*u1 + v3[i]);
            float g2 = 0.5f*dgam - gfd;
            term += fmaxf(kap*gam - g2, 0.f);
        }
        g_rowloss[idx] = term - 3.f*kap;
    }
}

// ---------------- kernel 6: fused CSR aggregation + GIN 2-layer MLP -------
// grid = 128 blocks, 256 threads, dynamic smem
template<int DIN>
__global__ void gin_kernel(const float* __restrict__ hin,
    const unsigned* __restrict__ kmask,
    const float* __restrict__ eps_ptr, int t_idx,
    const float* __restrict__ W1, const float* __restrict__ b1,
    const float* __restrict__ W2, const float* __restrict__ b2,
    float* __restrict__ hout)
{
    extern __shared__ float sm2[];
    float* sW1  = sm2;                    // DIN*64
    float* sW2  = sW1 + DIN*64;           // 64*64
    float* sAgg = sW2 + 64*64;            // 32*DIN
    float* sHid = sAgg + 32*DIN;          // 32*64
    __shared__ unsigned skm[16];
    const int tid = threadIdx.x;
    const int nodeBase = blockIdx.x * 32;
    const int b = nodeBase >> 9;

    for (int i = tid; i < DIN*64; i += 256) sW1[i] = W1[i];
    for (int i = tid; i < 64*64; i += 256)  sW2[i] = W2[i];
    if (tid < 16) skm[tid] = kmask ? kmask[b*16 + tid] : 0xffffffffu;
    __syncthreads();

    const int w = tid >> 5, lane = tid & 31;
    const float eps1 = 1.f + eps_ptr[t_idx];

    for (int nn = 0; nn < 4; nn++) {
        int nl = w*4 + nn;
        int node = nodeBase + nl;
        int loc = node & 511;
        bool rk = (skm[loc >> 5] >> (loc & 31)) & 1u;
        float acc[DIN/32];
        #pragma unroll
        for (int q = 0; q < DIN/32; q++) acc[q] = 0.f;
        if (rk) {
            int deg = g_ndeg[node];
            const unsigned short* L = g_nbr + (size_t)node*NBCAP;
            #pragma unroll 4
            for (int n = 0; n < deg; n++) {
                int j = L[n];
                if ((skm[j >> 5] >> (j & 31)) & 1u) {
                    const float* hr = hin + ((size_t)(b*Nx + j))*DIN;
                    #pragma unroll
                    for (int q = 0; q < DIN/32; q++) acc[q] += hr[lane + 32*q];
                }
            }
        }
        const float* hs = hin + (size_t)node*DIN;
        #pragma unroll
        for (int q = 0; q < DIN/32; q++)
            sAgg[nl*DIN + lane + 32*q] = eps1*hs[lane + 32*q] + acc[q];
    }
    __syncthreads();

    {
        int h2 = tid & 31, g8 = tid >> 5;
        float r[4][2];
        float b1a = b1[2*h2], b1b = b1[2*h2+1];
        #pragma unroll
        for (int k = 0; k < 4; k++) { r[k][0] = b1a; r[k][1] = b1b; }
        for (int d = 0; d < DIN; d++) {
            float2 wv = *(const float2*)&sW1[d*64 + 2*h2];
            #pragma unroll
            for (int k = 0; k < 4; k++) {
                float a = sAgg[(g8 + 8*k)*DIN + d];
                r[k][0] += a * wv.x; r[k][1] += a * wv.y;
            }
        }
        #pragma unroll
        for (int k = 0; k < 4; k++) {
            float2 o; o.x = fmaxf(r[k][0], 0.f); o.y = fmaxf(r[k][1], 0.f);
            *(float2*)&sHid[(g8 + 8*k)*64 + 2*h2] = o;
        }
    }
    __syncthreads();

    {
        int h2 = tid & 31, g8 = tid >> 5;
        float r[4][2];
        float b2a = b2[2*h2], b2b = b2[2*h2+1];
        #pragma unroll
        for (int k = 0; k < 4; k++) { r[k][0] = b2a; r[k][1] = b2b; }
        for (int d = 0; d < 64; d++) {
            float2 wv = *(const float2*)&sW2[d*64 + 2*h2];
            #pragma unroll
            for (int k = 0; k < 4; k++) {
                float a = sHid[(g8 + 8*k)*64 + d];
                r[k][0] += a * wv.x; r[k][1] += a * wv.y;
            }
        }
        #pragma unroll
        for (int k = 0; k < 4; k++) {
            float2 o; o.x = fmaxf(r[k][0], 0.f); o.y = fmaxf(r[k][1], 0.f);
            *(float2*)&hout[((size_t)(nodeBase + g8 + 8*k))*64 + 2*h2] = o;
        }
    }
}

// ---------------- kernel 7: readout stage 1 (partial column sums) ---------
__global__ void final_part_kernel(const float* __restrict__ X)
{
    int b = blockIdx.x, pp = blockIdx.y, t = threadIdx.x;
    int n0 = pp * 64;
    float a = 0.f;
    if (t < 128) {
        for (int n = n0; n < n0 + 64; n++) a += X[((size_t)(b*Nx + n))*Dx + t];
    } else {
        int layer = (t - 128) >> 6, c = (t - 128) & 63;
        const float* H = &g_h[layer][0];
        for (int n = n0; n < n0 + 64; n++) a += H[(b*Nx + n)*Hx + c];
    }
    g_part[(b*8 + pp)*320 + t] = a;
}

// ---------------- kernel 8: readout stage 2 (matmul + loss) ---------------
__global__ void final_out_kernel(const float* __restrict__ outW,
                                 const float* __restrict__ outb,
                                 float* __restrict__ dout, int out_size)
{
    __shared__ float S[320];
    __shared__ float L[320];
    int b = blockIdx.x, t = threadIdx.x;
    float a = 0.f;
    #pragma unroll
    for (int p2 = 0; p2 < 8; p2++) a += g_part[(b*8 + p2)*320 + t];
    S[t] = a;
    float lp = 0.f;
    for (int i = t; i < BN; i += 320) lp += g_rowloss[i];
    L[t] = lp;
    __syncthreads();
    if (t < OUTC) {
        float o = outb[t];
        for (int f = 0; f < 320; f++) o += S[f] * outW[f*OUTC + t];
        dout[b*OUTC + t] = o;
    }
    if (t < 32) {
        float l = 0.f;
        for (int i = t; i < 320; i += 32) l += L[i];
        #pragma unroll
        for (int o = 16; o > 0; o >>= 1) l += __shfl_xor_sync(0xffffffffu, l, o);
        if (b == 0 && t == 0 && out_size > Bx*OUTC) dout[Bx*OUTC] = l;
    }
}

// ---------------- launch ----------------
extern "C" void kernel_launch(void* const* d_in, const int* in_sizes, int n_in,
                              void* d_out, int out_size) {
    const float* X    = (const float*)d_in[0];
    const float* A    = (const float*)d_in[1];
    const int*   p    = (const int*)  d_in[2];
    const float* cW1  = (const float*)d_in[3];
    const float* cb1  = (const float*)d_in[4];
    const float* cW2  = (const float*)d_in[5];
    const float* cb2  = (const float*)d_in[6];
    const float* wmW1 = (const float*)d_in[7];
    const float* wmb1 = (const float*)d_in[8];
    const float* wmW2 = (const float*)d_in[9];
    const float* wmb2 = (const float*)d_in[10];
    const float* wmW3 = (const float*)d_in[11];
    const float* wmb3 = (const float*)d_in[12];
    const float* fW1  = (const float*)d_in[13];
    const float* fb1  = (const float*)d_in[14];
    const float* fW2  = (const float*)d_in[15];
    const float* fb2  = (const float*)d_in[16];
    const float* eps  = (const float*)d_in[17];
    const float* g0W1 = (const float*)d_in[18];
    const float* g0b1 = (const float*)d_in[19];
    const float* g0W2 = (const float*)d_in[20];
    const float* g0b2 = (const float*)d_in[21];
    const float* g1W1 = (const float*)d_in[22];
    const float* g1b1 = (const float*)d_in[23];
    const float* g1W2 = (const float*)d_in[24];
    const float* g1b2 = (const float*)d_in[25];
    const float* g2W1 = (const float*)d_in[26];
    const float* g2b1 = (const float*)d_in[27];
    const float* g2W2 = (const float*)d_in[28];
    const float* g2b2 = (const float*)d_in[29];
    const float* outW = (const float*)d_in[30];
    const float* outb = (const float*)d_in[31];
    float* dout = (float*)d_out;

    float *h0_p, *h1_p, *h2_p;
    unsigned *km1_p, *km2_p;
    cudaGetSymbolAddress((void**)&h0_p, g_h);
    h1_p = h0_p + BN*Hx;
    h2_p = h0_p + 2*BN*Hx;
    cudaGetSymbolAddress((void**)&km1_p, g_kmask1);
    cudaGetSymbolAddress((void**)&km2_p, g_kmask2);

    cudaFuncSetAttribute((const void*)node_mlps_tiled,
        cudaFuncAttributeMaxDynamicSharedMemorySize, 57600);
    cudaFuncSetAttribute((const void*)gin_kernel<128>,
        cudaFuncAttributeMaxDynamicSharedMemorySize, 73728);
    cudaFuncSetAttribute((const void*)gin_kernel<64>,
        cudaFuncAttributeMaxDynamicSharedMemorySize, 49152);

    adjmask_kernel<<<BN/8, 256>>>(A);
    node_mlps_tiled<<<dim3(BN/32, 5), 256, 57600>>>(X,
        cW1, cb1, cW2, cb2, fW1, fb1, fW2, fb2,
        wmW1, wmb1, wmW2, wmb2, wmW3, wmb3);
    prune_kernel<<<Bx, Nx>>>(p);
    curv1_kernel<<<dim3(64, Bx), 256>>>();
    curv2_kernel<<<dim3(64, Bx), 256>>>();

    gin_kernel<128><<<BN/32, 256, 73728>>>(X,    nullptr, eps, 0, g0W1, g0b1, g0W2, g0b2, h0_p);
    gin_kernel<64> <<<BN/32, 256, 49152>>>(h0_p, km1_p,   eps, 1, g1W1, g1b1, g1W2, g1b2, h1_p);
    gin_kernel<64> <<<BN/32, 256, 49152>>>(h1_p, km2_p,   eps, 2, g2W1, g2b1, g2W2, g2b2, h2_p);

    final_part_kernel<<<dim3(Bx, 8), 320>>>(X);
    final_out_kernel<<<Bx, 320>>>(outW, outb, dout, out_size);
}

// round 9
// speedup vs baseline: 1.2803x; 1.1429x over previous
#include <cuda_runtime.h>
#include <math.h>

#define Bx 8
#define Nx 512
#define Dx 128
#define Hx 64
#define FNx 3
#define NLx 3
#define OUTC 10
#define BN (Bx*Nx)
#define NBCAP 128
#define NB 128          // grid size: all blocks co-resident on 148 SMs

// ---------------- device scratch (static, no allocation) ----------------
__device__ float    g_kap[BN];
__device__ float    g_f[FNx][BN];
__device__ float    g_m1;
__device__ unsigned g_adj[BN*16];           // 512-bit row bitmask per node
__device__ unsigned short g_nbr[BN*NBCAP];  // CSR neighbor lists
__device__ int      g_ndeg[BN];
__device__ unsigned g_kmask1[Bx*16];
__device__ unsigned g_kmask2[Bx*16];
__device__ float    g_deg[BN];
__device__ float    g_u1[FNx][BN];
__device__ float    g_gamma[FNx][BN];
__device__ float    g_df[FNx][BN];
__device__ float    g_fdf[FNx][BN];
__device__ float    g_rowloss[BN];
__device__ float    g_loss;
__device__ float    g_h[NLx][BN*Hx];
__device__ float    g_part[Bx*8*320];
__device__ unsigned g_barcnt[8];            // monotonic across replays

// ---------------- software grid barrier (all NB blocks co-resident) -------
__device__ __forceinline__ void gridbar(int id)
{
    __syncthreads();
    __threadfence();
    if (threadIdx.x == 0) {
        unsigned tk = atomicAdd(&g_barcnt[id], 1u);
        unsigned base = tk - (tk & (NB - 1));   // NB is power of 2
        while ((*(volatile unsigned*)&g_barcnt[id]) - base < NB) { }
        __threadfence();
    }
    __syncthreads();
}

// ---------------- gin sub-phase (fused CSR aggregation + 2-layer MLP) -----
template<int DIN>
__device__ void gin_phase(float* sm, const float* __restrict__ hin,
    const unsigned* __restrict__ kmask, float eps1,
    const float* __restrict__ W1, const float* __restrict__ b1,
    const float* __restrict__ W2, const float* __restrict__ b2,
    float* __restrict__ hout)
{
    float* sW1  = sm;                    // DIN*64
    float* sW2  = sW1 + DIN*64;          // 64*64
    float* sAgg = sW2 + 64*64;           // 32*DIN
    float* sHid = sAgg + 32*DIN;         // 32*64
    unsigned* skm = (unsigned*)(sHid + 2048);
    const int tid = threadIdx.x;
    const int nodeBase = blockIdx.x * 32;
    const int b = nodeBase >> 9;

    for (int i = tid; i < DIN*64; i += 256) sW1[i] = W1[i];
    for (int i = tid; i < 64*64; i += 256)  sW2[i] = W2[i];
    if (tid < 16) skm[tid] = kmask ? kmask[b*16 + tid] : 0xffffffffu;
    __syncthreads();

    const int w = tid >> 5, lane = tid & 31;

    for (int nn = 0; nn < 4; nn++) {
        int nl = w*4 + nn;
        int node = nodeBase + nl;
        int loc = node & 511;
        bool rk = (skm[loc >> 5] >> (loc & 31)) & 1u;
        float acc[DIN/32];
        #pragma unroll
        for (int q = 0; q < DIN/32; q++) acc[q] = 0.f;
        if (rk) {
            int deg = g_ndeg[node];
            const unsigned short* L = g_nbr + (size_t)node*NBCAP;
            #pragma unroll 4
            for (int n = 0; n < deg; n++) {
                int j = L[n];
                if ((skm[j >> 5] >> (j & 31)) & 1u) {
                    const float* hr = hin + ((size_t)(b*Nx + j))*DIN;
                    #pragma unroll
                    for (int q = 0; q < DIN/32; q++) acc[q] += hr[lane + 32*q];
                }
            }
        }
        const float* hs = hin + (size_t)node*DIN;
        #pragma unroll
        for (int q = 0; q < DIN/32; q++)
            sAgg[nl*DIN + lane + 32*q] = eps1*hs[lane + 32*q] + acc[q];
    }
    __syncthreads();

    {   // hidden layer
        int h2 = tid & 31, g8 = tid >> 5;
        float r[4][2];
        float b1a = b1[2*h2], b1b = b1[2*h2+1];
        #pragma unroll
        for (int k = 0; k < 4; k++) { r[k][0] = b1a; r[k][1] = b1b; }
        for (int d = 0; d < DIN; d++) {
            float2 wv = *(const float2*)&sW1[d*64 + 2*h2];
            #pragma unroll
            for (int k = 0; k < 4; k++) {
                float a = sAgg[(g8 + 8*k)*DIN + d];
                r[k][0] += a * wv.x; r[k][1] += a * wv.y;
            }
        }
        #pragma unroll
        for (int k = 0; k < 4; k++) {
            float2 o; o.x = fmaxf(r[k][0], 0.f); o.y = fmaxf(r[k][1], 0.f);
            *(float2*)&sHid[(g8 + 8*k)*64 + 2*h2] = o;
        }
    }
    __syncthreads();

    {   // output layer
        int h2 = tid & 31, g8 = tid >> 5;
        float r[4][2];
        float b2a = b2[2*h2], b2b = b2[2*h2+1];
        #pragma unroll
        for (int k = 0; k < 4; k++) { r[k][0] = b2a; r[k][1] = b2b; }
        for (int d = 0; d < 64; d++) {
            float2 wv = *(const float2*)&sW2[d*64 + 2*h2];
            #pragma unroll
            for (int k = 0; k < 4; k++) {
                float a = sHid[(g8 + 8*k)*64 + d];
                r[k][0] += a * wv.x; r[k][1] += a * wv.y;
            }
        }
        #pragma unroll
        for (int k = 0; k < 4; k++) {
            float2 o; o.x = fmaxf(r[k][0], 0.f); o.y = fmaxf(r[k][1], 0.f);
            *(float2*)&hout[((size_t)(nodeBase + g8 + 8*k))*64 + 2*h2] = o;
        }
    }
    __syncthreads();
}

// ---------------- the megakernel ------------------------------------------
__global__ __launch_bounds__(256, 1)
void mega_kernel(const float* __restrict__ X, const float* __restrict__ A,
    const int* __restrict__ p_ptr,
    const float* __restrict__ cW1, const float* __restrict__ cb1,
    const float* __restrict__ cW2, const float* __restrict__ cb2,
    const float* __restrict__ wmW1, const float* __restrict__ wmb1,
    const float* __restrict__ wmW2, const float* __restrict__ wmb2,
    const float* __restrict__ wmW3, const float* __restrict__ wmb3,
    const float* __restrict__ fW1, const float* __restrict__ fb1,
    const float* __restrict__ fW2, const float* __restrict__ fb2,
    const float* __restrict__ eps,
    const float* __restrict__ g0W1, const float* __restrict__ g0b1,
    const float* __restrict__ g0W2, const float* __restrict__ g0b2,
    const float* __restrict__ g1W1, const float* __restrict__ g1b1,
    const float* __restrict__ g1W2, const float* __restrict__ g1b2,
    const float* __restrict__ g2W1, const float* __restrict__ g2b1,
    const float* __restrict__ g2W2, const float* __restrict__ g2b2,
    const float* __restrict__ outW, const float* __restrict__ outb,
    float* __restrict__ dout, int out_size)
{
    extern __shared__ float sm[];
    const int tid = threadIdx.x, bid = blockIdx.x;
    const int w = tid >> 5, lane = tid & 31;
    const unsigned full = 0xffffffffu;

    // ================= PHASE 1a: adjacency compress + CSR (4 rows/warp) ===
    {
        int warpG = bid*8 + w;               // 0..1023
        for (int k = 0; k < 4; k++) {
            int r = warpG*4 + k;
            const float* Ar = A + (size_t)r * Nx;
            unsigned myword = 0;
            #pragma unroll
            for (int c = 0; c < 16; c++) {
                float v = Ar[c*32 + lane];
                unsigned m = __ballot_sync(full, v != 0.f);
                if (lane == c) myword = m;
            }
            if (lane < 16) g_adj[(size_t)r*16 + lane] = myword;
            unsigned wv = (lane < 16) ? myword : 0u;
            int cnt = __popc(wv);
            int ex = cnt;
            #pragma unroll
            for (int o = 1; o < 32; o <<= 1) {
                int nv = __shfl_up_sync(full, ex, o);
                if (lane >= o) ex += nv;
            }
            int total = __shfl_sync(full, ex, 15);
            ex -= cnt;
            if (lane < 16) {
                int pos = ex;
                unsigned bits = wv;
                while (bits) {
                    int j = __ffs(bits) - 1; bits &= bits - 1;
                    if (pos < NBCAP)
                        g_nbr[(size_t)r*NBCAP + pos] = (unsigned short)(lane*32 + j);
                    pos++;
                }
            }
            if (lane == 0) g_ndeg[r] = (total < NBCAP) ? total : NBCAP;
        }
    }

    // ================= PHASE 1b: node MLPs (curv + 3 fn), group = bid =====
    {
        float* sX   = sm;                  // 32*128
        float* sW1s = sm + 4096;           // 128*64
        float* sHid = sm + 4096 + 8192;    // 32*64
        float* sW2v = sHid + 2048;         // 64
        int nodeBase = bid * 32;
        __syncthreads();
        for (int i = tid; i < 32*Dx; i += 256) sX[i] = X[(size_t)nodeBase*Dx + i];

        for (int m = 0; m < 4; m++) {
            const float* W1 = (m == 0) ? cW1 : fW1 + (size_t)(m-1)*Dx*Hx;
            const float* B1 = (m == 0) ? cb1 : fb1 + (m-1)*Hx;
            const float* W2 = (m == 0) ? cW2 : fW2 + (m-1)*Hx;
            float B2 = (m == 0) ? cb2[0] : fb2[m-1];
            __syncthreads();
            for (int i = tid; i < Dx*Hx; i += 256) sW1s[i] = W1[i];
            if (tid < 64) sW2v[tid] = W2[tid];
            __syncthreads();
            {
                int h2 = tid & 31, g8 = tid >> 5;
                float r[4][2];
                float b1a = B1[2*h2], b1b = B1[2*h2+1];
                #pragma unroll
                for (int k = 0; k < 4; k++) { r[k][0] = b1a; r[k][1] = b1b; }
                for (int d = 0; d < Dx; d++) {
                    float2 wv2 = *(const float2*)&sW1s[d*64 + 2*h2];
                    #pragma unroll
                    for (int k = 0; k < 4; k++) {
                        float a = sX[(g8 + 8*k)*Dx + d];
                        r[k][0] += a * wv2.x; r[k][1] += a * wv2.y;
                    }
                }
                #pragma unroll
                for (int k = 0; k < 4; k++) {
                    float2 o; o.x = fmaxf(r[k][0], 0.f); o.y = fmaxf(r[k][1], 0.f);
                    *(float2*)&sHid[(g8 + 8*k)*64 + 2*h2] = o;
                }
            }
            __syncthreads();
            for (int nn = 0; nn < 4; nn++) {
                int nl = w*4 + nn;
                float v = sHid[nl*64 + lane] * sW2v[lane]
                        + sHid[nl*64 + 32 + lane] * sW2v[32 + lane];
                #pragma unroll
                for (int o = 16; o > 0; o >>= 1) v += __shfl_xor_sync(full, v, o);
                if (lane == 0) {
                    float sig = 1.f / (1.f + expf(-(v + B2)));
                    int node = nodeBase + nl;
                    if (m == 0) g_kap[node] = sig; else g_f[m-1][node] = sig;
                }
            }
        }
        if (bid == 0) {   // scalar m1 = sigmoid(MLP(1))
            float* s1 = sm + 14400;
            float* s2 = s1 + 64;
            __syncthreads();
            if (tid < 64) s1[tid] = fmaxf(wmW1[tid] + wmb1[tid], 0.f);
            __syncthreads();
            if (tid < 32) {
                float a = wmb2[tid];
                #pragma unroll
                for (int i = 0; i < 64; i++) a += s1[i] * wmW2[i*32 + tid];
                s2[tid] = fmaxf(a, 0.f);
            }
            __syncthreads();
            if (tid == 0) {
                float s = wmb3[0];
                #pragma unroll
                for (int i = 0; i < 32; i++) s += s2[i] * wmW3[i];
                g_m1 = 1.f / (1.f + expf(-s));
            }
        }
    }

    gridbar(0);   // kap/f/m1/adj ready

    // ================= PHASE 2: prune (blocks 0-7) + curv1 + gin0 =========
    if (bid < Bx) {   // prune batch b = bid
        int b = bid;
        float* sv = sm;         // 512
        float* so = sm + 512;   // 512
        for (int i = tid; i < Nx; i += 256) { float v = g_kap[b*Nx + i]; sv[i] = v; so[i] = v; }
        __syncthreads();
        for (int k = 2; k <= Nx; k <<= 1)
            for (int j = k >> 1; j > 0; j >>= 1) {
                for (int i = tid; i < Nx; i += 256) {
                    int ixj = i ^ j;
                    if (ixj > i) {
                        float a = sv[i], c = sv[ixj];
                        bool up = ((i & k) == 0);
                        if ((a > c) == up) { sv[i] = c; sv[ixj] = a; }
                    }
                }
                __syncthreads();
            }
        int p = *p_ptr;
        float keepA0 = 1.f, keepA1 = 1.f, keepB0 = 1.f, keepB1 = 1.f;
        for (int phase = 0; phase < 2; phase++) {
            int kk = (Nx * p * (phase+1)) / 100;
            bool rem0 = false, rem1 = false;
            if (kk >= 1) {
                float T = sv[Nx - kk];
                int c0 = __syncthreads_count(so[tid] > T);
                int c1 = __syncthreads_count(so[tid+256] > T);
                int need = kk - (c0 + c1);
                rem0 = so[tid] > T; rem1 = so[tid+256] > T;
                if (!rem0 && so[tid] == T && need > 0) {
                    int r = 0;
                    for (int j = 0; j < tid; j++) if (so[j] == T) r++;
                    if (r < need) rem0 = true;
                }
                if (!rem1 && so[tid+256] == T && need > 0) {
                    int r = 0;
                    for (int j = 0; j < tid+256; j++) if (so[j] == T) r++;
                    if (r < need) rem1 = true;
                }
            }
            if (phase == 0) { keepA0 = rem0?0.f:1.f; keepA1 = rem1?0.f:1.f; }
            else           { keepB0 = rem0?0.f:1.f; keepB1 = rem1?0.f:1.f; }
            __syncthreads();
        }
        unsigned mA0 = __ballot_sync(full, keepA0 != 0.f);
        unsigned mA1 = __ballot_sync(full, keepA1 != 0.f);
        unsigned mB0 = __ballot_sync(full, keepA0*keepB0 != 0.f);
        unsigned mB1 = __ballot_sync(full, keepA1*keepB1 != 0.f);
        if (lane == 0) {
            g_kmask1[b*16 + w]     = mA0;
            g_kmask1[b*16 + 8 + w] = mA1;
            g_kmask2[b*16 + w]     = mB0;
            g_kmask2[b*16 + 8 + w] = mB1;
        }
        __syncthreads();
    }

    {   // curv pass 1: batch = bid>>4, 32 rows per block, 4 rows/warp
        int b2 = bid >> 4;
        int rowbase = (bid & 15) * 32;
        __syncthreads();
        for (int i = tid; i < FNx*Nx; i += 256)
            sm[i] = g_f[i >> 9][b2*Nx + (i & 511)];
        __syncthreads();
        float m1 = g_m1;
        unsigned myw[4];
        #pragma unroll
        for (int k = 0; k < 4; k++) {
            int row = rowbase + w*4 + k;
            myw[k] = (lane < 16) ? g_adj[(size_t)(b2*Nx + row)*16 + lane] : 0u;
        }
        int degi[4];
        #pragma unroll
        for (int k = 0; k < 4; k++) degi[k] = __popc(myw[k]);
        float u1[4][FNx], u2[4][FNx];
        #pragma unroll
        for (int k = 0; k < 4; k++)
            #pragma unroll
            for (int i = 0; i < FNx; i++) { u1[k][i] = 0.f; u2[k][i] = 0.f; }
        #pragma unroll
        for (int c = 0; c < 16; c++) {
            float fv[FNx];
            #pragma unroll
            for (int i = 0; i < FNx; i++) fv[i] = sm[i*512 + c*32 + lane];
            #pragma unroll
            for (int k = 0; k < 4; k++) {
                unsigned bits = __shfl_sync(full, myw[k], c);
                float sel = (float)((bits >> lane) & 1u);
                #pragma unroll
                for (int i = 0; i < FNx; i++) {
                    u1[k][i] += sel * fv[i];
                    u2[k][i] += sel * fv[i] * fv[i];
                }
            }
        }
        #pragma unroll
        for (int o = 16; o > 0; o >>= 1) {
            #pragma unroll
            for (int k = 0; k < 4; k++) {
                degi[k] += __shfl_xor_sync(full, degi[k], o);
                #pragma unroll
                for (int i = 0; i < FNx; i++) {
                    u1[k][i] += __shfl_xor_sync(full, u1[k][i], o);
                    u2[k][i] += __shfl_xor_sync(full, u2[k][i], o);
                }
            }
        }
        if (lane == 0) {
            #pragma unroll
            for (int k = 0; k < 4; k++) {
                int row = rowbase + w*4 + k;
                int idx = b2*Nx + row;
                float deg = (float)degi[k];
                g_deg[idx] = deg;
                #pragma unroll
                for (int i = 0; i < FNx; i++) {
                    float fr = sm[i*512 + row];
                    g_u1[i][idx] = u1[k][i];
                    float gam = 0.5f*m1*(fr*fr*deg - 2.f*fr*u1[k][i] + u2[k][i]);
                    float df  = m1*(fr*deg - u1[k][i]);
                    g_gamma[i][idx] = gam; g_df[i][idx] = df; g_fdf[i][idx] = fr*df;
                }
            }
        }
        __syncthreads();
    }

    {   // gin layer 0 (needs adj + X only)
        float eps1 = 1.f + eps[0];
        gin_phase<128>(sm, X, nullptr, eps1, g0W1, g0b1, g0W2, g0b2, &g_h[0][0]);
    }

    gridbar(1);   // gamma/df/fdf, kmask1, h0 ready

    // ================= PHASE 3: curv2 + gin1 ==============================
    {   // curv pass 2
        int b2 = bid >> 4;
        int rowbase = (bid & 15) * 32;
        float* sgam = sm;            // 3*512
        float* sdf  = sm + 1536;     // 3*512
        float* sfd  = sm + 3072;     // 3*512
        for (int i = tid; i < FNx*Nx; i += 256) {
            int f = i >> 9, j = i & 511, id2 = b2*Nx + j;
            sgam[f*512 + j] = g_gamma[f][id2];
            sdf[f*512 + j]  = g_df[f][id2];
            sfd[f*512 + j]  = g_fdf[f][id2];
        }
        __syncthreads();
        float m1 = g_m1;
        unsigned myw[4];
        #pragma unroll
        for (int k = 0; k < 4; k++) {
            int row = rowbase + w*4 + k;
            myw[k] = (lane < 16) ? g_adj[(size_t)(b2*Nx + row)*16 + lane] : 0u;
        }
        float v1[4][FNx], v2[4][FNx], v3[4][FNx];
        #pragma unroll
        for (int k = 0; k < 4; k++)
            #pragma unroll
            for (int i = 0; i < FNx; i++) { v1[k][i]=0.f; v2[k][i]=0.f; v3[k][i]=0.f; }
        #pragma unroll
        for (int c = 0; c < 16; c++) {
            int j = c*32 + lane;
            float gv[FNx], dv[FNx], fv[FNx];
            #pragma unroll
            for (int i = 0; i < FNx; i++) {
                gv[i] = sgam[i*512 + j]; dv[i] = sdf[i*512 + j]; fv[i] = sfd[i*512 + j];
            }
            #pragma unroll
            for (int k = 0; k < 4; k++) {
                unsigned bits = __shfl_sync(full, myw[k], c);
                float sel = (float)((bits >> lane) & 1u);
                #pragma unroll
                for (int i = 0; i < FNx; i++) {
                    v1[k][i] += sel * gv[i];
                    v2[k][i] += sel * dv[i];
                    v3[k][i] += sel * fv[i];
                }
            }
        }
        #pragma unroll
        for (int o = 16; o > 0; o >>= 1) {
            #pragma unroll
            for (int k = 0; k < 4; k++)
                #pragma unroll
                for (int i = 0; i < FNx; i++) {
                    v1[k][i] += __shfl_xor_sync(full, v1[k][i], o);
                    v2[k][i] += __shfl_xor_sync(full, v2[k][i], o);
                    v3[k][i] += __shfl_xor_sync(full, v3[k][i], o);
                }
        }
        if (lane == 0) {
            #pragma unroll
            for (int k = 0; k < 4; k++) {
                int row = rowbase + w*4 + k;
                int idx = b2*Nx + row;
                float deg = g_deg[idx], kap = g_kap[idx];
                float term = 0.f;
                #pragma unroll
                for (int i = 0; i < FNx; i++) {
                    float gam = sgam[i*512 + row], df = sdf[i*512 + row], fdf = sfd[i*512 + row];
                    float fr = g_f[i][idx];
                    float u1v = g_u1[i][idx];
                    float dgam = m1*(gam*deg - v1[k][i]);
                    float gfd  = 0.5f*m1*(fdf*deg - fr*v2[k][i] - df*u1v + v3[k][i]);
                    float g2 = 0.5f*dgam - gfd;
                    term += fmaxf(kap*gam - g2, 0.f);
                }
                g_rowloss[idx] = term - 3.f*kap;
            }
        }
        __syncthreads();
    }
    {   // gin layer 1
        float eps1 = 1.f + eps[1];
        gin_phase<64>(sm, &g_h[0][0], g_kmask1, eps1, g1W1, g1b1, g1W2, g1b2, &g_h[1][0]);
    }

    gridbar(2);   // h1, rowloss ready

    // ================= PHASE 4: gin2 ======================================
    {
        float eps1 = 1.f + eps[2];
        gin_phase<64>(sm, &g_h[1][0], g_kmask2, eps1, g2W1, g2b1, g2W2, g2b2, &g_h[2][0]);
    }

    gridbar(3);   // h2 ready

    // ================= PHASE 5: readout partials + loss reduce ============
    if (bid < 64) {
        int b = bid >> 3, pp = bid & 7;
        int n0 = pp * 64;
        for (int f = tid; f < 320; f += 256) {
            float a = 0.f;
            if (f < 128) {
                for (int n = n0; n < n0 + 64; n++) a += X[((size_t)(b*Nx + n))*Dx + f];
            } else {
                int layer = (f - 128) >> 6, c = (f - 128) & 63;
                const float* H = &g_h[layer][0];
                for (int n = n0; n < n0 + 64; n++) a += H[(b*Nx + n)*Hx + c];
            }
            g_part[(b*8 + pp)*320 + f] = a;
        }
    } else if (bid == 64) {
        float lp = 0.f;
        for (int i = tid; i < BN; i += 256) lp += g_rowloss[i];
        sm[tid] = lp;
        __syncthreads();
        for (int o = 128; o > 0; o >>= 1) { if (tid < o) sm[tid] += sm[tid + o]; __syncthreads(); }
        if (tid == 0) g_loss = sm[0];
    }

    gridbar(4);   // partials + loss ready

    // ================= PHASE 6: final output GEMM =========================
    if (bid < Bx) {
        int b = bid;
        float* S = sm;
        for (int f = tid; f < 320; f += 256) {
            float a = 0.f;
            #pragma unroll
            for (int p2 = 0; p2 < 8; p2++) a += g_part[(b*8 + p2)*320 + f];
            S[f] = a;
        }
        __syncthreads();
        if (tid < OUTC) {
            float o = outb[tid];
            for (int f = 0; f < 320; f++) o += S[f] * outW[f*OUTC + tid];
            dout[b*OUTC + tid] = o;
        }
        if (b == 0 && tid == OUTC && out_size > Bx*OUTC) dout[Bx*OUTC] = g_loss;
    }
}

// ---------------- launch ----------------
extern "C" void kernel_launch(void* const* d_in, const int* in_sizes, int n_in,
                              void* d_out, int out_size) {
    const float* X    = (const float*)d_in[0];
    const float* A    = (const float*)d_in[1];
    const int*   p    = (const int*)  d_in[2];
    const float* cW1  = (const float*)d_in[3];
    const float* cb1  = (const float*)d_in[4];
    const float* cW2  = (const float*)d_in[5];
    const float* cb2  = (const float*)d_in[6];
    const float* wmW1 = (const float*)d_in[7];
    const float* wmb1 = (const float*)d_in[8];
    const float* wmW2 = (const float*)d_in[9];
    const float* wmb2 = (const float*)d_in[10];
    const float* wmW3 = (const float*)d_in[11];
    const float* wmb3 = (const float*)d_in[12];
    const float* fW1  = (const float*)d_in[13];
    const float* fb1  = (const float*)d_in[14];
    const float* fW2  = (const float*)d_in[15];
    const float* fb2  = (const float*)d_in[16];
    const float* eps  = (const float*)d_in[17];
    const float* g0W1 = (const float*)d_in[18];
    const float* g0b1 = (const float*)d_in[19];
    const float* g0W2 = (const float*)d_in[20];
    const float* g0b2 = (const float*)d_in[21];
    const float* g1W1 = (const float*)d_in[22];
    const float* g1b1 = (const float*)d_in[23];
    const float* g1W2 = (const float*)d_in[24];
    const float* g1b2 = (const float*)d_in[25];
    const float* g2W1 = (const float*)d_in[26];
    const float* g2b1 = (const float*)d_in[27];
    const float* g2W2 = (const float*)d_in[28];
    const float* g2b2 = (const float*)d_in[29];
    const float* outW = (const float*)d_in[30];
    const float* outb = (const float*)d_in[31];
    float* dout = (float*)d_out;

    // dyn smem: max phase = gin<128>: 18432 floats + 16 uints = 73792 B
    static const int SMEM = 73792;
    cudaFuncSetAttribute((const void*)mega_kernel,
        cudaFuncAttributeMaxDynamicSharedMemorySize, SMEM);

    mega_kernel<<<NB, 256, SMEM>>>(X, A, p,
        cW1, cb1, cW2, cb2,
        wmW1, wmb1, wmW2, wmb2, wmW3, wmb3,
        fW1, fb1, fW2, fb2, eps,
        g0W1, g0b1, g0W2, g0b2,
        g1W1, g1b1, g1W2, g1b2,
        g2W1, g2b1, g2W2, g2b2,
        outW, outb, dout, out_size);
}

// round 10
// speedup vs baseline: 1.7600x; 1.3746x over previous
#include <cuda_runtime.h>
#include <math.h>

#define Bx 8
#define Nx 512
#define Dx 128
#define Hx 64
#define FNx 3
#define NLx 3
#define OUTC 10
#define BN (Bx*Nx)
#define NBCAP 128
#define NB 128          // grid size: all blocks co-resident
#define NT 512          // threads per block (16 warps)

// ---------------- device scratch (static, no allocation) ----------------
__device__ float    g_kap[BN];
__device__ float    g_f[FNx][BN];
__device__ float    g_m1;
__device__ unsigned g_adj[BN*16];
__device__ unsigned short g_nbr[BN*NBCAP];
__device__ int      g_ndeg[BN];
__device__ unsigned g_kmask1[Bx*16];
__device__ unsigned g_kmask2[Bx*16];
__device__ float    g_deg[BN];
__device__ float    g_u1[FNx][BN];
__device__ float    g_gamma[FNx][BN];
__device__ float    g_df[FNx][BN];
__device__ float    g_fdf[FNx][BN];
__device__ float    g_rowloss[BN];
__device__ float    g_loss;
__device__ float    g_h[NLx][BN*Hx];
__device__ float    g_part[Bx*16*320];
__device__ unsigned g_barcnt[8];            // monotonic across graph replays

// ---------------- software grid barrier (all NB blocks co-resident) -------
__device__ __forceinline__ void gridbar(int id)
{
    __syncthreads();
    __threadfence();
    if (threadIdx.x == 0) {
        unsigned tk = atomicAdd(&g_barcnt[id], 1u);
        unsigned base = tk - (tk & (NB - 1));
        while ((*(volatile unsigned*)&g_barcnt[id]) - base < NB) { }
        __threadfence();
    }
    __syncthreads();
}

// ---------------- gin sub-phase (512 threads): CSR agg + 2-layer MLP ------
template<int DIN>
__device__ void gin_phase(float* sm, const float* __restrict__ hin,
    const unsigned* __restrict__ kmask, float eps1,
    const float* __restrict__ W1, const float* __restrict__ b1,
    const float* __restrict__ W2, const float* __restrict__ b2,
    float* __restrict__ hout)
{
    float* sW1  = sm;                    // DIN*64
    float* sW2  = sW1 + DIN*64;          // 64*64
    float* sAgg = sW2 + 64*64;           // 32*DIN
    float* sHid = sAgg + 32*DIN;         // 32*64
    unsigned* skm = (unsigned*)(sHid + 2048);
    const int tid = threadIdx.x;
    const int nodeBase = blockIdx.x * 32;
    const int b = nodeBase >> 9;

    for (int i = tid; i < DIN*64; i += NT) sW1[i] = W1[i];
    for (int i = tid; i < 64*64; i += NT)  sW2[i] = W2[i];
    if (tid < 16) skm[tid] = kmask ? kmask[b*16 + tid] : 0xffffffffu;
    __syncthreads();

    const int w = tid >> 5, lane = tid & 31;

    // aggregation: 16 warps x 2 nodes
    for (int nn = 0; nn < 2; nn++) {
        int nl = w*2 + nn;
        int node = nodeBase + nl;
        int loc = node & 511;
        bool rk = (skm[loc >> 5] >> (loc & 31)) & 1u;
        float acc[DIN/32];
        #pragma unroll
        for (int q = 0; q < DIN/32; q++) acc[q] = 0.f;
        if (rk) {
            int deg = g_ndeg[node];
            const unsigned short* L = g_nbr + (size_t)node*NBCAP;
            #pragma unroll 4
            for (int n = 0; n < deg; n++) {
                int j = L[n];
                if ((skm[j >> 5] >> (j & 31)) & 1u) {
                    const float* hr = hin + ((size_t)(b*Nx + j))*DIN;
                    #pragma unroll
                    for (int q = 0; q < DIN/32; q++) acc[q] += hr[lane + 32*q];
                }
            }
        }
        const float* hs = hin + (size_t)node*DIN;
        #pragma unroll
        for (int q = 0; q < DIN/32; q++)
            sAgg[nl*DIN + lane + 32*q] = eps1*hs[lane + 32*q] + acc[q];
    }
    __syncthreads();

    {   // hidden layer: thread = 1 col x 4 nodes (512 = 64 cols x 8 groups)
        int col = tid & 63, grp = tid >> 6;
        float r[4];
        float bc = b1[col];
        #pragma unroll
        for (int k = 0; k < 4; k++) r[k] = bc;
        for (int d = 0; d < DIN; d++) {
            float wv = sW1[d*64 + col];
            #pragma unroll
            for (int k = 0; k < 4; k++)
                r[k] += sAgg[(grp + 8*k)*DIN + d] * wv;
        }
        #pragma unroll
        for (int k = 0; k < 4; k++)
            sHid[(grp + 8*k)*64 + col] = fmaxf(r[k], 0.f);
    }
    __syncthreads();

    {   // output layer
        int col = tid & 63, grp = tid >> 6;
        float r[4];
        float bc = b2[col];
        #pragma unroll
        for (int k = 0; k < 4; k++) r[k] = bc;
        for (int d = 0; d < 64; d++) {
            float wv = sW2[d*64 + col];
            #pragma unroll
            for (int k = 0; k < 4; k++)
                r[k] += sHid[(grp + 8*k)*64 + d] * wv;
        }
        #pragma unroll
        for (int k = 0; k < 4; k++)
            hout[((size_t)(nodeBase + grp + 8*k))*64 + col] = fmaxf(r[k], 0.f);
    }
    __syncthreads();
}

// ---------------- the megakernel ------------------------------------------
__global__ __launch_bounds__(NT, 1)
void mega_kernel(const float* __restrict__ X, const float* __restrict__ A,
    const int* __restrict__ p_ptr,
    const float* __restrict__ cW1, const float* __restrict__ cb1,
    const float* __restrict__ cW2, const float* __restrict__ cb2,
    const float* __restrict__ wmW1, const float* __restrict__ wmb1,
    const float* __restrict__ wmW2, const float* __restrict__ wmb2,
    const float* __restrict__ wmW3, const float* __restrict__ wmb3,
    const float* __restrict__ fW1, const float* __restrict__ fb1,
    const float* __restrict__ fW2, const float* __restrict__ fb2,
    const float* __restrict__ eps,
    const float* __restrict__ g0W1, const float* __restrict__ g0b1,
    const float* __restrict__ g0W2, const float* __restrict__ g0b2,
    const float* __restrict__ g1W1, const float* __restrict__ g1b1,
    const float* __restrict__ g1W2, const float* __restrict__ g1b2,
    const float* __restrict__ g2W1, const float* __restrict__ g2b1,
    const float* __restrict__ g2W2, const float* __restrict__ g2b2,
    const float* __restrict__ outW, const float* __restrict__ outb,
    float* __restrict__ dout, int out_size)
{
    extern __shared__ float sm[];
    __shared__ int wcnt[16];
    const int tid = threadIdx.x, bid = blockIdx.x;
    const int w = tid >> 5, lane = tid & 31;
    const unsigned full = 0xffffffffu;

    // ================= PHASE 1a: adjacency compress + CSR (2 rows/warp) ===
    {
        int warpG = bid*16 + w;              // 0..2047
        for (int k = 0; k < 2; k++) {
            int r = warpG*2 + k;
            const float* Ar = A + (size_t)r * Nx;
            unsigned myword = 0;
            #pragma unroll
            for (int c = 0; c < 16; c++) {
                float v = Ar[c*32 + lane];
                unsigned m = __ballot_sync(full, v != 0.f);
                if (lane == c) myword = m;
            }
            if (lane < 16) g_adj[(size_t)r*16 + lane] = myword;
            unsigned wv = (lane < 16) ? myword : 0u;
            int cnt = __popc(wv);
            int ex = cnt;
            #pragma unroll
            for (int o = 1; o < 32; o <<= 1) {
                int nv = __shfl_up_sync(full, ex, o);
                if (lane >= o) ex += nv;
            }
            int total = __shfl_sync(full, ex, 15);
            ex -= cnt;
            if (lane < 16) {
                int pos = ex;
                unsigned bits = wv;
                while (bits) {
                    int j = __ffs(bits) - 1; bits &= bits - 1;
                    if (pos < NBCAP)
                        g_nbr[(size_t)r*NBCAP + pos] = (unsigned short)(lane*32 + j);
                    pos++;
                }
            }
            if (lane == 0) g_ndeg[r] = (total < NBCAP) ? total : NBCAP;
        }
    }

    // ================= PHASE 1b: node MLPs (curv + 3 fn) ==================
    {
        float* sX   = sm;                  // 32*128 = 4096
        float* sW1s = sm + 4096;           // 128*64 = 8192
        float* sHid = sm + 4096 + 8192;    // 32*64  = 2048
        float* sW2v = sHid + 2048;         // 64
        int nodeBase = bid * 32;
        __syncthreads();
        for (int i = tid; i < 32*Dx; i += NT) sX[i] = X[(size_t)nodeBase*Dx + i];

        for (int m = 0; m < 4; m++) {
            const float* W1 = (m == 0) ? cW1 : fW1 + (size_t)(m-1)*Dx*Hx;
            const float* B1 = (m == 0) ? cb1 : fb1 + (m-1)*Hx;
            const float* W2 = (m == 0) ? cW2 : fW2 + (m-1)*Hx;
            float B2 = (m == 0) ? cb2[0] : fb2[m-1];
            __syncthreads();
            for (int i = tid; i < Dx*Hx; i += NT) sW1s[i] = W1[i];
            if (tid < 64) sW2v[tid] = W2[tid];
            __syncthreads();
            {   // hidden: 1 col x 4 nodes per thread
                int col = tid & 63, grp = tid >> 6;
                float r[4];
                float bc = B1[col];
                #pragma unroll
                for (int k = 0; k < 4; k++) r[k] = bc;
                for (int d = 0; d < Dx; d++) {
                    float wv2 = sW1s[d*64 + col];
                    #pragma unroll
                    for (int k = 0; k < 4; k++)
                        r[k] += sX[(grp + 8*k)*Dx + d] * wv2;
                }
                #pragma unroll
                for (int k = 0; k < 4; k++)
                    sHid[(grp + 8*k)*64 + col] = fmaxf(r[k], 0.f);
            }
            __syncthreads();
            // scalar head: warp per node, 2 rounds
            for (int nn = 0; nn < 2; nn++) {
                int nl = w*2 + nn;
                float v = sHid[nl*64 + lane] * sW2v[lane]
                        + sHid[nl*64 + 32 + lane] * sW2v[32 + lane];
                #pragma unroll
                for (int o = 16; o > 0; o >>= 1) v += __shfl_xor_sync(full, v, o);
                if (lane == 0) {
                    float sig = 1.f / (1.f + expf(-(v + B2)));
                    int node = nodeBase + nl;
                    if (m == 0) g_kap[node] = sig; else g_f[m-1][node] = sig;
                }
            }
        }
        if (bid == 0) {   // scalar m1 = sigmoid(MLP(1))
            float* s1 = sm + 14400;
            float* s2 = s1 + 64;
            __syncthreads();
            if (tid < 64) s1[tid] = fmaxf(wmW1[tid] + wmb1[tid], 0.f);
            __syncthreads();
            if (tid < 32) {
                float a = wmb2[tid];
                #pragma unroll
                for (int i = 0; i < 64; i++) a += s1[i] * wmW2[i*32 + tid];
                s2[tid] = fmaxf(a, 0.f);
            }
            __syncthreads();
            if (tid == 0) {
                float s = wmb3[0];
                #pragma unroll
                for (int i = 0; i < 32; i++) s += s2[i] * wmW3[i];
                g_m1 = 1.f / (1.f + expf(-s));
            }
        }
    }

    gridbar(0);   // kap/f/m1/adj ready

    // ================= PHASE 2: prune (blocks 0-7) + curv1 + gin0 =========
    if (bid < Bx) {   // prune batch b = bid; 1 element per thread
        int b = bid;
        float* sv = sm;         // 512
        float* so = sm + 512;   // 512
        float v = g_kap[b*Nx + tid];
        sv[tid] = v; so[tid] = v;
        __syncthreads();
        for (int k = 2; k <= Nx; k <<= 1)
            for (int j = k >> 1; j > 0; j >>= 1) {
                int ixj = tid ^ j;
                if (ixj > tid) {
                    float a = sv[tid], c = sv[ixj];
                    bool up = ((tid & k) == 0);
                    if ((a > c) == up) { sv[tid] = c; sv[ixj] = a; }
                }
                __syncthreads();
            }
        int p = *p_ptr;
        float keepA = 1.f, keepB = 1.f;
        for (int phase = 0; phase < 2; phase++) {
            int kk = (Nx * p * (phase+1)) / 100;
            bool removed = false;
            if (kk >= 1) {
                float T = sv[Nx - kk];
                int cgt = __syncthreads_count(so[tid] > T);
                int need = kk - cgt;
                removed = (so[tid] > T);
                bool eq = (so[tid] == T) && (need > 0);
                unsigned bal = __ballot_sync(full, eq);
                if (lane == 0) wcnt[w] = __popc(bal);
                __syncthreads();
                int off = 0;
                #pragma unroll
                for (int i = 0; i < 16; i++) if (i < w) off += wcnt[i];
                int rank = off + __popc(bal & ((1u << lane) - 1u));
                if (eq && rank < need) removed = true;
            }
            if (phase == 0) keepA = removed ? 0.f : 1.f;
            else           keepB = removed ? 0.f : 1.f;
            __syncthreads();
        }
        unsigned mA = __ballot_sync(full, keepA != 0.f);
        unsigned mB = __ballot_sync(full, keepA * keepB != 0.f);
        if (lane == 0) { g_kmask1[b*16 + w] = mA; g_kmask2[b*16 + w] = mB; }
        __syncthreads();
    }

    {   // curv pass 1: batch = bid>>4, 32 rows/block, 2 rows/warp
        int b2 = bid >> 4;
        int rowbase = (bid & 15) * 32;
        __syncthreads();
        for (int i = tid; i < FNx*Nx; i += NT)
            sm[i] = g_f[i >> 9][b2*Nx + (i & 511)];
        __syncthreads();
        float m1 = g_m1;
        unsigned myw[2];
        #pragma unroll
        for (int k = 0; k < 2; k++) {
            int row = rowbase + w*2 + k;
            myw[k] = (lane < 16) ? g_adj[(size_t)(b2*Nx + row)*16 + lane] : 0u;
        }
        int degi[2];
        #pragma unroll
        for (int k = 0; k < 2; k++) degi[k] = __popc(myw[k]);
        float u1[2][FNx], u2[2][FNx];
        #pragma unroll
        for (int k = 0; k < 2; k++)
            #pragma unroll
            for (int i = 0; i < FNx; i++) { u1[k][i] = 0.f; u2[k][i] = 0.f; }
        #pragma unroll
        for (int c = 0; c < 16; c++) {
            float fv[FNx];
            #pragma unroll
            for (int i = 0; i < FNx; i++) fv[i] = sm[i*512 + c*32 + lane];
            #pragma unroll
            for (int k = 0; k < 2; k++) {
                unsigned bits = __shfl_sync(full, myw[k], c);
                float sel = (float)((bits >> lane) & 1u);
                #pragma unroll
                for (int i = 0; i < FNx; i++) {
                    u1[k][i] += sel * fv[i];
                    u2[k][i] += sel * fv[i] * fv[i];
                }
            }
        }
        #pragma unroll
        for (int o = 16; o > 0; o >>= 1) {
            #pragma unroll
            for (int k = 0; k < 2; k++) {
                degi[k] += __shfl_xor_sync(full, degi[k], o);
                #pragma unroll
                for (int i = 0; i < FNx; i++) {
                    u1[k][i] += __shfl_xor_sync(full, u1[k][i], o);
                    u2[k][i] += __shfl_xor_sync(full, u2[k][i], o);
                }
            }
        }
        if (lane == 0) {
            #pragma unroll
            for (int k = 0; k < 2; k++) {
                int row = rowbase + w*2 + k;
                int idx = b2*Nx + row;
                float deg = (float)degi[k];
                g_deg[idx] = deg;
                #pragma unroll
                for (int i = 0; i < FNx; i++) {
                    float fr = sm[i*512 + row];
                    g_u1[i][idx] = u1[k][i];
                    float gam = 0.5f*m1*(fr*fr*deg - 2.f*fr*u1[k][i] + u2[k][i]);
                    float df  = m1*(fr*deg - u1[k][i]);
                    g_gamma[i][idx] = gam; g_df[i][idx] = df; g_fdf[i][idx] = fr*df;
                }
            }
        }
        __syncthreads();
    }

    {   // gin layer 0
        float eps1 = 1.f + eps[0];
        gin_phase<128>(sm, X, nullptr, eps1, g0W1, g0b1, g0W2, g0b2, &g_h[0][0]);
    }

    gridbar(1);   // gamma/df/fdf, kmask1, h0 ready

    // ================= PHASE 3: curv2 + gin1 ==============================
    {   // curv pass 2
        int b2 = bid >> 4;
        int rowbase = (bid & 15) * 32;
        float* sgam = sm;            // 3*512
        float* sdf  = sm + 1536;
        float* sfd  = sm + 3072;
        for (int i = tid; i < FNx*Nx; i += NT) {
            int f = i >> 9, j = i & 511, id2 = b2*Nx + j;
            sgam[f*512 + j] = g_gamma[f][id2];
            sdf[f*512 + j]  = g_df[f][id2];
            sfd[f*512 + j]  = g_fdf[f][id2];
        }
        __syncthreads();
        float m1 = g_m1;
        unsigned myw[2];
        #pragma unroll
        for (int k = 0; k < 2; k++) {
            int row = rowbase + w*2 + k;
            myw[k] = (lane < 16) ? g_adj[(size_t)(b2*Nx + row)*16 + lane] : 0u;
        }
        float v1[2][FNx], v2[2][FNx], v3[2][FNx];
        #pragma unroll
        for (int k = 0; k < 2; k++)
            #pragma unroll
            for (int i = 0; i < FNx; i++) { v1[k][i]=0.f; v2[k][i]=0.f; v3[k][i]=0.f; }
        #pragma unroll
        for (int c = 0; c < 16; c++) {
            int j = c*32 + lane;
            float gv[FNx], dv[FNx], fv[FNx];
            #pragma unroll
            for (int i = 0; i < FNx; i++) {
                gv[i] = sgam[i*512 + j]; dv[i] = sdf[i*512 + j]; fv[i] = sfd[i*512 + j];
            }
            #pragma unroll
            for (int k = 0; k < 2; k++) {
                unsigned bits = __shfl_sync(full, myw[k], c);
                float sel = (float)((bits >> lane) & 1u);
                #pragma unroll
                for (int i = 0; i < FNx; i++) {
                    v1[k][i] += sel * gv[i];
                    v2[k][i] += sel * dv[i];
                    v3[k][i] += sel * fv[i];
                }
            }
        }
        #pragma unroll
        for (int o = 16; o > 0; o >>= 1) {
            #pragma unroll
            for (int k = 0; k < 2; k++)
                #pragma unroll
                for (int i = 0; i < FNx; i++) {
                    v1[k][i] += __shfl_xor_sync(full, v1[k][i], o);
                    v2[k][i] += __shfl_xor_sync(full, v2[k][i], o);
                    v3[k][i] += __shfl_xor_sync(full, v3[k][i], o);
                }
        }
        if (lane == 0) {
            #pragma unroll
            for (int k = 0; k < 2; k++) {
                int row = rowbase + w*2 + k;
                int idx = b2*Nx + row;
                float deg = g_deg[idx], kap = g_kap[idx];
                float term = 0.f;
                #pragma unroll
                for (int i = 0; i < FNx; i++) {
                    float gam = sgam[i*512 + row], df = sdf[i*512 + row], fdf = sfd[i*512 + row];
                    float fr = g_f[i][idx];
                    float u1v = g_u1[i][idx];
                    float dgam = m1*(gam*deg - v1[k][i]);
                    float gfd  = 0.5f*m1*(fdf*deg - fr*v2[k][i] - df*u1v + v3[k][i]);
                    float g2 = 0.5f*dgam - gfd;
                    term += fmaxf(kap*gam - g2, 0.f);
                }
                g_rowloss[idx] = term - 3.f*kap;
            }
        }
        __syncthreads();
    }
    {   // gin layer 1
        float eps1 = 1.f + eps[1];
        gin_phase<64>(sm, &g_h[0][0], g_kmask1, eps1, g1W1, g1b1, g1W2, g1b2, &g_h[1][0]);
    }

    gridbar(2);   // h1, rowloss ready

    // ================= PHASE 4: gin2 ======================================
    {
        float eps1 = 1.f + eps[2];
        gin_phase<64>(sm, &g_h[1][0], g_kmask2, eps1, g2W1, g2b1, g2W2, g2b2, &g_h[2][0]);
    }

    gridbar(3);   // h2 ready

    // ================= PHASE 5: readout partials (all 128 blocks) + loss ==
    {
        int b = bid >> 4, pp = bid & 15;
        int n0 = pp * 32;
        if (tid < 320) {
            int f = tid;
            float a0 = 0.f, a1 = 0.f;
            if (f < 128) {
                const float* Xb = X + ((size_t)(b*Nx + n0))*Dx + f;
                #pragma unroll 4
                for (int n = 0; n < 32; n += 2) { a0 += Xb[n*Dx]; a1 += Xb[(n+1)*Dx]; }
            } else {
                int layer = (f - 128) >> 6, c = (f - 128) & 63;
                const float* Hb = &g_h[layer][(b*Nx + n0)*Hx + c];
                #pragma unroll 4
                for (int n = 0; n < 32; n += 2) { a0 += Hb[n*Hx]; a1 += Hb[(n+1)*Hx]; }
            }
            g_part[(b*16 + pp)*320 + f] = a0 + a1;
        }
        if (bid == NB-1) {   // loss reduction on last block
            float lp = 0.f;
            #pragma unroll
            for (int i = tid; i < BN; i += NT) lp += g_rowloss[i];
            float* L = sm + 1024;
            L[tid] = lp;
            __syncthreads();
            for (int o = 256; o > 0; o >>= 1) { if (tid < o) L[tid] += L[tid + o]; __syncthreads(); }
            if (tid == 0) g_loss = L[0];
        }
    }

    gridbar(4);   // partials + loss ready

    // ================= PHASE 6: final output GEMM =========================
    if (bid < Bx) {
        int b = bid;
        float* S = sm;
        if (tid < 320) {
            float a = 0.f;
            #pragma unroll
            for (int p2 = 0; p2 < 16; p2++) a += g_part[(b*16 + p2)*320 + tid];
            S[tid] = a;
        }
        __syncthreads();
        if (tid < OUTC) {
            float o = outb[tid];
            for (int f = 0; f < 320; f++) o += S[f] * outW[f*OUTC + tid];
            dout[b*OUTC + tid] = o;
        }
        if (b == 0 && tid == OUTC && out_size > Bx*OUTC) dout[Bx*OUTC] = g_loss;
    }
}

// ---------------- launch ----------------
extern "C" void kernel_launch(void* const* d_in, const int* in_sizes, int n_in,
                              void* d_out, int out_size) {
    const float* X    = (const float*)d_in[0];
    const float* A    = (const float*)d_in[1];
    const int*   p    = (const int*)  d_in[2];
    const float* cW1  = (const float*)d_in[3];
    const float* cb1  = (const float*)d_in[4];
    const float* cW2  = (const float*)d_in[5];
    const float* cb2  = (const float*)d_in[6];
    const float* wmW1 = (const float*)d_in[7];
    const float* wmb1 = (const float*)d_in[8];
    const float* wmW2 = (const float*)d_in[9];
    const float* wmb2 = (const float*)d_in[10];
    const float* wmW3 = (const float*)d_in[11];
    const float* wmb3 = (const float*)d_in[12];
    const float* fW1  = (const float*)d_in[13];
    const float* fb1  = (const float*)d_in[14];
    const float* fW2  = (const float*)d_in[15];
    const float* fb2  = (const float*)d_in[16];
    const float* eps  = (const float*)d_in[17];
    const float* g0W1 = (const float*)d_in[18];
    const float* g0b1 = (const float*)d_in[19];
    const float* g0W2 = (const float*)d_in[20];
    const float* g0b2 = (const float*)d_in[21];
    const float* g1W1 = (const float*)d_in[22];
    const float* g1b1 = (const float*)d_in[23];
    const float* g1W2 = (const float*)d_in[24];
    const float* g1b2 = (const float*)d_in[25];
    const float* g2W1 = (const float*)d_in[26];
    const float* g2b1 = (const float*)d_in[27];
    const float* g2W2 = (const float*)d_in[28];
    const float* g2b2 = (const float*)d_in[29];
    const float* outW = (const float*)d_in[30];
    const float* outb = (const float*)d_in[31];
    float* dout = (float*)d_out;

    // dyn smem: max phase = gin<128>: 18432 floats + 16 uints = 73792 B
    static const int SMEM = 73792;
    cudaFuncSetAttribute((const void*)mega_kernel,
        cudaFuncAttributeMaxDynamicSharedMemorySize, SMEM);

    mega_kernel<<<NB, NT, SMEM>>>(X, A, p,
        cW1, cb1, cW2, cb2,
        wmW1, wmb1, wmW2, wmb2, wmW3, wmb3,
        fW1, fb1, fW2, fb2, eps,
        g0W1, g0b1, g0W2, g0b2,
        g1W1, g1b1, g1W2, g1b2,
        g2W1, g2b1, g2W2, g2b2,
        outW, outb, dout, out_size);
}

// round 11
// speedup vs baseline: 1.8130x; 1.0301x over previous
#include <cuda_runtime.h>
#include <math.h>

#define Bx 8
#define Nx 512
#define Dx 128
#define Hx 64
#define FNx 3
#define NLx 3
#define OUTC 10
#define BN (Bx*Nx)
#define NBCAP 128
#define NB 128          // grid size: all blocks co-resident
#define NT 512          // threads per block (16 warps)

// ---------------- device scratch (static, no allocation) ----------------
__device__ float    g_kap[BN];
__device__ float    g_f[FNx][BN];
__device__ float    g_m1;
__device__ unsigned g_adj[BN*16];
__device__ unsigned short g_nbr[BN*NBCAP];
__device__ int      g_ndeg[BN];
__device__ unsigned g_kmask1[Bx*16];
__device__ unsigned g_kmask2[Bx*16];
__device__ float    g_deg[BN];
__device__ float    g_u1[FNx][BN];
__device__ float    g_gamma[FNx][BN];
__device__ float    g_df[FNx][BN];
__device__ float    g_fdf[FNx][BN];
__device__ float    g_rowloss[BN];
__device__ float    g_loss;
__device__ __align__(16) float g_h[NLx][BN*Hx];
__device__ float    g_part[Bx*16*320];
__device__ unsigned g_barcnt[8];            // monotonic across graph replays

// ---------------- software grid barrier (all NB blocks co-resident) -------
__device__ __forceinline__ void gridbar(int id)
{
    __syncthreads();
    __threadfence();
    if (threadIdx.x == 0) {
        unsigned tk = atomicAdd(&g_barcnt[id], 1u);
        unsigned base = tk - (tk & (NB - 1));
        while ((*(volatile unsigned*)&g_barcnt[id]) - base < NB) { }
        __threadfence();
    }
    __syncthreads();
}

// ---------------- gin sub-phase: CSR agg + 2-layer MLP + column partials --
// partCol: base column in g_part for this layer's readout partials
template<int DIN>
__device__ void gin_phase(float* sm, const float* __restrict__ hin,
    const unsigned* __restrict__ kmask, float eps1,
    const float* __restrict__ W1, const float* __restrict__ b1,
    const float* __restrict__ W2, const float* __restrict__ b2,
    float* __restrict__ hout, int partCol)
{
    float* sW1  = sm;                    // DIN*64
    float* sW2  = sW1 + DIN*64;          // 64*64
    float* sAgg = sW2 + 64*64;           // 32*DIN  (reused as sRed in epilogue)
    float* sHid = sAgg + 32*DIN;         // 32*64
    unsigned* skm = (unsigned*)(sHid + 2048);
    const int tid = threadIdx.x;
    const int nodeBase = blockIdx.x * 32;
    const int b = nodeBase >> 9;
    const int pp = (nodeBase >> 5) & 15;

    for (int i = tid; i < DIN*64; i += NT) sW1[i] = W1[i];
    for (int i = tid; i < 64*64; i += NT)  sW2[i] = W2[i];
    if (tid < 16) skm[tid] = kmask ? kmask[b*16 + tid] : 0xffffffffu;
    __syncthreads();

    const int w = tid >> 5, lane = tid & 31;

    // aggregation: 16 warps x 2 nodes, vectorized loads
    for (int nn = 0; nn < 2; nn++) {
        int nl = w*2 + nn;
        int node = nodeBase + nl;
        int loc = node & 511;
        bool rk = (skm[loc >> 5] >> (loc & 31)) & 1u;
        if (DIN == 128) {
            float4 acc = make_float4(0.f, 0.f, 0.f, 0.f);
            if (rk) {
                int deg = g_ndeg[node];
                const unsigned short* L = g_nbr + (size_t)node*NBCAP;
                #pragma unroll 4
                for (int n = 0; n < deg; n++) {
                    int j = L[n];
                    if ((skm[j >> 5] >> (j & 31)) & 1u) {
                        float4 v = ((const float4*)(hin + ((size_t)(b*Nx + j))*DIN))[lane];
                        acc.x += v.x; acc.y += v.y; acc.z += v.z; acc.w += v.w;
                    }
                }
            }
            float4 hv = ((const float4*)(hin + (size_t)node*DIN))[lane];
            float4 o;
            o.x = eps1*hv.x + acc.x; o.y = eps1*hv.y + acc.y;
            o.z = eps1*hv.z + acc.z; o.w = eps1*hv.w + acc.w;
            *(float4*)&sAgg[nl*DIN + lane*4] = o;
        } else {
            float2 acc = make_float2(0.f, 0.f);
            if (rk) {
                int deg = g_ndeg[node];
                const unsigned short* L = g_nbr + (size_t)node*NBCAP;
                #pragma unroll 4
                for (int n = 0; n < deg; n++) {
                    int j = L[n];
                    if ((skm[j >> 5] >> (j & 31)) & 1u) {
                        float2 v = ((const float2*)(hin + ((size_t)(b*Nx + j))*DIN))[lane];
                        acc.x += v.x; acc.y += v.y;
                    }
                }
            }
            float2 hv = ((const float2*)(hin + (size_t)node*DIN))[lane];
            float2 o;
            o.x = eps1*hv.x + acc.x; o.y = eps1*hv.y + acc.y;
            *(float2*)&sAgg[nl*DIN + lane*2] = o;
        }
    }
    __syncthreads();

    {   // hidden layer: thread = 1 col x 4 nodes (activation reads broadcast)
        int col = tid & 63, grp = tid >> 6;
        float r[4];
        float bc = b1[col];
        #pragma unroll
        for (int k = 0; k < 4; k++) r[k] = bc;
        #pragma unroll 4
        for (int d = 0; d < DIN; d++) {
            float wv = sW1[d*64 + col];
            #pragma unroll
            for (int k = 0; k < 4; k++)
                r[k] += sAgg[(grp + 8*k)*DIN + d] * wv;
        }
        #pragma unroll
        for (int k = 0; k < 4; k++)
            sHid[(grp + 8*k)*64 + col] = fmaxf(r[k], 0.f);
    }
    __syncthreads();

    {   // output layer + fused column partials
        int col = tid & 63, grp = tid >> 6;
        float r[4];
        float bc = b2[col];
        #pragma unroll
        for (int k = 0; k < 4; k++) r[k] = bc;
        #pragma unroll 4
        for (int d = 0; d < 64; d++) {
            float wv = sW2[d*64 + col];
            #pragma unroll
            for (int k = 0; k < 4; k++)
                r[k] += sHid[(grp + 8*k)*64 + d] * wv;
        }
        float psum = 0.f;
        #pragma unroll
        for (int k = 0; k < 4; k++) {
            float v = fmaxf(r[k], 0.f);
            psum += v;
            if (hout) hout[((size_t)(nodeBase + grp + 8*k))*64 + col] = v;
        }
        sAgg[grp*64 + col] = psum;    // sAgg free after hidden stage
    }
    __syncthreads();
    if (tid < 64) {
        float s = 0.f;
        #pragma unroll
        for (int g = 0; g < 8; g++) s += sAgg[g*64 + tid];
        g_part[(b*16 + pp)*320 + partCol + tid] = s;
    }
    __syncthreads();
}

// ---------------- the megakernel ------------------------------------------
__global__ __launch_bounds__(NT, 1)
void mega_kernel(const float* __restrict__ X, const float* __restrict__ A,
    const int* __restrict__ p_ptr,
    const float* __restrict__ cW1, const float* __restrict__ cb1,
    const float* __restrict__ cW2, const float* __restrict__ cb2,
    const float* __restrict__ wmW1, const float* __restrict__ wmb1,
    const float* __restrict__ wmW2, const float* __restrict__ wmb2,
    const float* __restrict__ wmW3, const float* __restrict__ wmb3,
    const float* __restrict__ fW1, const float* __restrict__ fb1,
    const float* __restrict__ fW2, const float* __restrict__ fb2,
    const float* __restrict__ eps,
    const float* __restrict__ g0W1, const float* __restrict__ g0b1,
    const float* __restrict__ g0W2, const float* __restrict__ g0b2,
    const float* __restrict__ g1W1, const float* __restrict__ g1b1,
    const float* __restrict__ g1W2, const float* __restrict__ g1b2,
    const float* __restrict__ g2W1, const float* __restrict__ g2b1,
    const float* __restrict__ g2W2, const float* __restrict__ g2b2,
    const float* __restrict__ outW, const float* __restrict__ outb,
    float* __restrict__ dout, int out_size)
{
    extern __shared__ float sm[];
    __shared__ int wcnt[16];
    const int tid = threadIdx.x, bid = blockIdx.x;
    const int w = tid >> 5, lane = tid & 31;
    const unsigned full = 0xffffffffu;

    // ================= PHASE 1a: adjacency compress + CSR (vectorized) ====
    {
        int warpG = bid*16 + w;              // 0..2047
        for (int k = 0; k < 2; k++) {
            int r = warpG*2 + k;
            const float4* Ar4 = (const float4*)(A + (size_t)r * Nx);
            unsigned wreg[4];
            #pragma unroll
            for (int g = 0; g < 4; g++) {
                float4 v = Ar4[g*32 + lane];
                unsigned nib = (unsigned)(v.x != 0.f)
                             | ((unsigned)(v.y != 0.f) << 1)
                             | ((unsigned)(v.z != 0.f) << 2)
                             | ((unsigned)(v.w != 0.f) << 3);
                unsigned wd = nib << (4*(lane & 7));
                wd |= __shfl_xor_sync(full, wd, 1);
                wd |= __shfl_xor_sync(full, wd, 2);
                wd |= __shfl_xor_sync(full, wd, 4);
                wreg[g] = wd;                // holds word index g*4 + (lane>>3)
            }
            // remap so lane t<16 holds word t
            unsigned srcl = (lane & 3) * 8;
            unsigned q0 = __shfl_sync(full, wreg[0], srcl);
            unsigned q1 = __shfl_sync(full, wreg[1], srcl);
            unsigned q2 = __shfl_sync(full, wreg[2], srcl);
            unsigned q3 = __shfl_sync(full, wreg[3], srcl);
            int g2 = lane >> 2;
            unsigned myword = (g2 == 0) ? q0 : (g2 == 1) ? q1 : (g2 == 2) ? q2 : q3;
            if (lane < 16) g_adj[(size_t)r*16 + lane] = myword;
            // CSR compaction (sorted by construction)
            unsigned wv = (lane < 16) ? myword : 0u;
            int cnt = __popc(wv);
            int ex = cnt;
            #pragma unroll
            for (int o = 1; o < 32; o <<= 1) {
                int nv = __shfl_up_sync(full, ex, o);
                if (lane >= o) ex += nv;
            }
            int total = __shfl_sync(full, ex, 15);
            ex -= cnt;
            if (lane < 16) {
                int pos = ex;
                unsigned bits = wv;
                while (bits) {
                    int j = __ffs(bits) - 1; bits &= bits - 1;
                    if (pos < NBCAP)
                        g_nbr[(size_t)r*NBCAP + pos] = (unsigned short)(lane*32 + j);
                    pos++;
                }
            }
            if (lane == 0) g_ndeg[r] = (total < NBCAP) ? total : NBCAP;
        }
    }

    // ================= PHASE 1b: node MLPs + X column partials ============
    {
        float* sX    = sm;                  // 32*128 = 4096
        float* sW1s  = sm + 4096;           // 128*64 = 8192
        float* sHid  = sm + 4096 + 8192;    // 32*64  = 2048
        float* sW2v  = sHid + 2048;         // 64
        float* sPartX= sm + 14400;          // 512
        int nodeBase = bid * 32;
        int b = bid >> 4, pp = bid & 15;
        __syncthreads();
        for (int i = tid; i < 32*Dx; i += NT) sX[i] = X[(size_t)nodeBase*Dx + i];
        __syncthreads();

        // X column partials for readout (cols 0..127)
        {
            int qtr = tid >> 7, col = tid & 127;
            float s = 0.f;
            #pragma unroll
            for (int n = 0; n < 8; n++) s += sX[(qtr*8 + n)*Dx + col];
            sPartX[qtr*128 + col] = s;
        }
        __syncthreads();
        if (tid < 128) {
            float s = sPartX[tid] + sPartX[128+tid] + sPartX[256+tid] + sPartX[384+tid];
            g_part[(b*16 + pp)*320 + tid] = s;
        }

        for (int m = 0; m < 4; m++) {
            const float* W1 = (m == 0) ? cW1 : fW1 + (size_t)(m-1)*Dx*Hx;
            const float* B1 = (m == 0) ? cb1 : fb1 + (m-1)*Hx;
            const float* W2 = (m == 0) ? cW2 : fW2 + (m-1)*Hx;
            float B2 = (m == 0) ? cb2[0] : fb2[m-1];
            __syncthreads();
            for (int i = tid; i < Dx*Hx; i += NT) sW1s[i] = W1[i];
            if (tid < 64) sW2v[tid] = W2[tid];
            __syncthreads();
            {   // hidden: 1 col x 4 nodes per thread
                int col = tid & 63, grp = tid >> 6;
                float r[4];
                float bc = B1[col];
                #pragma unroll
                for (int k = 0; k < 4; k++) r[k] = bc;
                #pragma unroll 4
                for (int d = 0; d < Dx; d++) {
                    float wv2 = sW1s[d*64 + col];
                    #pragma unroll
                    for (int k = 0; k < 4; k++)
                        r[k] += sX[(grp + 8*k)*Dx + d] * wv2;
                }
                #pragma unroll
                for (int k = 0; k < 4; k++)
                    sHid[(grp + 8*k)*64 + col] = fmaxf(r[k], 0.f);
            }
            __syncthreads();
            // scalar head: warp per node, 2 rounds
            for (int nn = 0; nn < 2; nn++) {
                int nl = w*2 + nn;
                float v = sHid[nl*64 + lane] * sW2v[lane]
                        + sHid[nl*64 + 32 + lane] * sW2v[32 + lane];
                #pragma unroll
                for (int o = 16; o > 0; o >>= 1) v += __shfl_xor_sync(full, v, o);
                if (lane == 0) {
                    float sig = 1.f / (1.f + expf(-(v + B2)));
                    int node = nodeBase + nl;
                    if (m == 0) g_kap[node] = sig; else g_f[m-1][node] = sig;
                }
            }
        }
        if (bid == 0) {   // scalar m1 = sigmoid(MLP(1))
            float* s1 = sm + 15000;
            float* s2 = s1 + 64;
            __syncthreads();
            if (tid < 64) s1[tid] = fmaxf(wmW1[tid] + wmb1[tid], 0.f);
            __syncthreads();
            if (tid < 32) {
                float a = wmb2[tid];
                #pragma unroll
                for (int i = 0; i < 64; i++) a += s1[i] * wmW2[i*32 + tid];
                s2[tid] = fmaxf(a, 0.f);
            }
            __syncthreads();
            if (tid == 0) {
                float s = wmb3[0];
                #pragma unroll
                for (int i = 0; i < 32; i++) s += s2[i] * wmW3[i];
                g_m1 = 1.f / (1.f + expf(-s));
            }
        }
    }

    gridbar(0);   // kap/f/m1/adj ready

    // ================= PHASE 2: prune (blocks 0-7) + curv1 + gin0 =========
    if (bid < Bx) {   // prune batch b = bid; 1 element per thread
        int b = bid;
        float* sv = sm;         // 512
        float* so = sm + 512;   // 512
        float v = g_kap[b*Nx + tid];
        sv[tid] = v; so[tid] = v;
        __syncthreads();
        for (int k = 2; k <= Nx; k <<= 1)
            for (int j = k >> 1; j > 0; j >>= 1) {
                int ixj = tid ^ j;
                if (ixj > tid) {
                    float a = sv[tid], c = sv[ixj];
                    bool up = ((tid & k) == 0);
                    if ((a > c) == up) { sv[tid] = c; sv[ixj] = a; }
                }
                __syncthreads();
            }
        int p = *p_ptr;
        float keepA = 1.f, keepB = 1.f;
        for (int phase = 0; phase < 2; phase++) {
            int kk = (Nx * p * (phase+1)) / 100;
            bool removed = false;
            if (kk >= 1) {
                float T = sv[Nx - kk];
                int cgt = __syncthreads_count(so[tid] > T);
                int need = kk - cgt;
                removed = (so[tid] > T);
                bool eq = (so[tid] == T) && (need > 0);
                unsigned bal = __ballot_sync(full, eq);
                if (lane == 0) wcnt[w] = __popc(bal);
                __syncthreads();
                int off = 0;
                #pragma unroll
                for (int i = 0; i < 16; i++) if (i < w) off += wcnt[i];
                int rank = off + __popc(bal & ((1u << lane) - 1u));
                if (eq && rank < need) removed = true;
            }
            if (phase == 0) keepA = removed ? 0.f : 1.f;
            else           keepB = removed ? 0.f : 1.f;
            __syncthreads();
        }
        unsigned mA = __ballot_sync(full, keepA != 0.f);
        unsigned mB = __ballot_sync(full, keepA * keepB != 0.f);
        if (lane == 0) { g_kmask1[b*16 + w] = mA; g_kmask2[b*16 + w] = mB; }
        __syncthreads();
    }

    {   // curv pass 1: batch = bid>>4, 32 rows/block, 2 rows/warp
        int b2 = bid >> 4;
        int rowbase = (bid & 15) * 32;
        __syncthreads();
        for (int i = tid; i < FNx*Nx; i += NT)
            sm[i] = g_f[i >> 9][b2*Nx + (i & 511)];
        __syncthreads();
        float m1 = g_m1;
        unsigned myw[2];
        #pragma unroll
        for (int k = 0; k < 2; k++) {
            int row = rowbase + w*2 + k;
            myw[k] = (lane < 16) ? g_adj[(size_t)(b2*Nx + row)*16 + lane] : 0u;
        }
        int degi[2];
        #pragma unroll
        for (int k = 0; k < 2; k++) degi[k] = __popc(myw[k]);
        float u1[2][FNx], u2[2][FNx];
        #pragma unroll
        for (int k = 0; k < 2; k++)
            #pragma unroll
            for (int i = 0; i < FNx; i++) { u1[k][i] = 0.f; u2[k][i] = 0.f; }
        #pragma unroll
        for (int c = 0; c < 16; c++) {
            float fv[FNx];
            #pragma unroll
            for (int i = 0; i < FNx; i++) fv[i] = sm[i*512 + c*32 + lane];
            #pragma unroll
            for (int k = 0; k < 2; k++) {
                unsigned bits = __shfl_sync(full, myw[k], c);
                float sel = (float)((bits >> lane) & 1u);
                #pragma unroll
                for (int i = 0; i < FNx; i++) {
                    u1[k][i] += sel * fv[i];
                    u2[k][i] += sel * fv[i] * fv[i];
                }
            }
        }
        #pragma unroll
        for (int o = 16; o > 0; o >>= 1) {
            #pragma unroll
            for (int k = 0; k < 2; k++) {
                degi[k] += __shfl_xor_sync(full, degi[k], o);
                #pragma unroll
                for (int i = 0; i < FNx; i++) {
                    u1[k][i] += __shfl_xor_sync(full, u1[k][i], o);
                    u2[k][i] += __shfl_xor_sync(full, u2[k][i], o);
                }
            }
        }
        if (lane == 0) {
            #pragma unroll
            for (int k = 0; k < 2; k++) {
                int row = rowbase + w*2 + k;
                int idx = b2*Nx + row;
                float deg = (float)degi[k];
                g_deg[idx] = deg;
                #pragma unroll
                for (int i = 0; i < FNx; i++) {
                    float fr = sm[i*512 + row];
                    g_u1[i][idx] = u1[k][i];
                    float gam = 0.5f*m1*(fr*fr*deg - 2.f*fr*u1[k][i] + u2[k][i]);
                    float df  = m1*(fr*deg - u1[k][i]);
                    g_gamma[i][idx] = gam; g_df[i][idx] = df; g_fdf[i][idx] = fr*df;
                }
            }
        }
        __syncthreads();
    }

    {   // gin layer 0 (partials -> cols 128..191)
        float eps1 = 1.f + eps[0];
        gin_phase<128>(sm, X, nullptr, eps1, g0W1, g0b1, g0W2, g0b2, &g_h[0][0], 128);
    }

    gridbar(1);   // gamma/df/fdf, kmask1, h0 ready

    // ================= PHASE 3: curv2 + gin1 ==============================
    {   // curv pass 2
        int b2 = bid >> 4;
        int rowbase = (bid & 15) * 32;
        float* sgam = sm;            // 3*512
        float* sdf  = sm + 1536;
        float* sfd  = sm + 3072;
        for (int i = tid; i < FNx*Nx; i += NT) {
            int f = i >> 9, j = i & 511, id2 = b2*Nx + j;
            sgam[f*512 + j] = g_gamma[f][id2];
            sdf[f*512 + j]  = g_df[f][id2];
            sfd[f*512 + j]  = g_fdf[f][id2];
        }
        __syncthreads();
        float m1 = g_m1;
        unsigned myw[2];
        #pragma unroll
        for (int k = 0; k < 2; k++) {
            int row = rowbase + w*2 + k;
            myw[k] = (lane < 16) ? g_adj[(size_t)(b2*Nx + row)*16 + lane] : 0u;
        }
        float v1[2][FNx], v2[2][FNx], v3[2][FNx];
        #pragma unroll
        for (int k = 0; k < 2; k++)
            #pragma unroll
            for (int i = 0; i < FNx; i++) { v1[k][i]=0.f; v2[k][i]=0.f; v3[k][i]=0.f; }
        #pragma unroll
        for (int c = 0; c < 16; c++) {
            int j = c*32 + lane;
            float gv[FNx], dv[FNx], fv[FNx];
            #pragma unroll
            for (int i = 0; i < FNx; i++) {
                gv[i] = sgam[i*512 + j]; dv[i] = sdf[i*512 + j]; fv[i] = sfd[i*512 + j];
            }
            #pragma unroll
            for (int k = 0; k < 2; k++) {
                unsigned bits = __shfl_sync(full, myw[k], c);
                float sel = (float)((bits >> lane) & 1u);
                #pragma unroll
                for (int i = 0; i < FNx; i++) {
                    v1[k][i] += sel * gv[i];
                    v2[k][i] += sel * dv[i];
                    v3[k][i] += sel * fv[i];
                }
            }
        }
        #pragma unroll
        for (int o = 16; o > 0; o >>= 1) {
            #pragma unroll
            for (int k = 0; k < 2; k++)
                #pragma unroll
                for (int i = 0; i < FNx; i++) {
                    v1[k][i] += __shfl_xor_sync(full, v1[k][i], o);
                    v2[k][i] += __shfl_xor_sync(full, v2[k][i], o);
                    v3[k][i] += __shfl_xor_sync(full, v3[k][i], o);
                }
        }
        if (lane == 0) {
            #pragma unroll
            for (int k = 0; k < 2; k++) {
                int row = rowbase + w*2 + k;
                int idx = b2*Nx + row;
                float deg = g_deg[idx], kap = g_kap[idx];
                float term = 0.f;
                #pragma unroll
                for (int i = 0; i < FNx; i++) {
                    float gam = sgam[i*512 + row], df = sdf[i*512 + row], fdf = sfd[i*512 + row];
                    float fr = g_f[i][idx];
                    float u1v = g_u1[i][idx];
                    float dgam = m1*(gam*deg - v1[k][i]);
                    float gfd  = 0.5f*m1*(fdf*deg - fr*v2[k][i] - df*u1v + v3[k][i]);
                    float g2 = 0.5f*dgam - gfd;
                    term += fmaxf(kap*gam - g2, 0.f);
                }
                g_rowloss[idx] = term - 3.f*kap;
            }
        }
        __syncthreads();
    }
    {   // gin layer 1 (partials -> cols 192..255)
        float eps1 = 1.f + eps[1];
        gin_phase<64>(sm, &g_h[0][0], g_kmask1, eps1, g1W1, g1b1, g1W2, g1b2, &g_h[1][0], 192);
    }

    gridbar(2);   // h1, rowloss ready

    // ================= PHASE 4: gin2 (no h write) + loss reduce ===========
    {
        float eps1 = 1.f + eps[2];
        gin_phase<64>(sm, &g_h[1][0], g_kmask2, eps1, g2W1, g2b1, g2W2, g2b2, nullptr, 256);
    }
    if (bid == NB-1) {   // loss reduction (rowloss ready since gridbar(2))
        float lp = 0.f;
        #pragma unroll
        for (int i = tid; i < BN; i += NT) lp += g_rowloss[i];
        float* L = sm;
        L[tid] = lp;
        __syncthreads();
        for (int o = 256; o > 0; o >>= 1) { if (tid < o) L[tid] += L[tid + o]; __syncthreads(); }
        if (tid == 0) g_loss = L[0];
    }

    gridbar(3);   // all partials + loss ready

    // ================= PHASE 5: final output GEMM =========================
    if (bid < Bx) {
        int b = bid;
        float* S = sm;
        if (tid < 320) {
            float a = 0.f;
            #pragma unroll
            for (int p2 = 0; p2 < 16; p2++) a += g_part[(b*16 + p2)*320 + tid];
            S[tid] = a;
        }
        __syncthreads();
        if (w < OUTC) {   // warp per output column
            float acc = 0.f;
            for (int f = lane; f < 320; f += 32) acc += S[f] * outW[f*OUTC + w];
            #pragma unroll
            for (int o = 16; o > 0; o >>= 1) acc += __shfl_xor_sync(full, acc, o);
            if (lane == 0) dout[b*OUTC + w] = acc + outb[w];
        }
        if (b == 0 && tid == 320 && out_size > Bx*OUTC) dout[Bx*OUTC] = g_loss;
    }
}

// ---------------- launch ----------------
extern "C" void kernel_launch(void* const* d_in, const int* in_sizes, int n_in,
                              void* d_out, int out_size) {
    const float* X    = (const float*)d_in[0];
    const float* A    = (const float*)d_in[1];
    const int*   p    = (const int*)  d_in[2];
    const float* cW1  = (const float*)d_in[3];
    const float* cb1  = (const float*)d_in[4];
    const float* cW2  = (const float*)d_in[5];
    const float* cb2  = (const float*)d_in[6];
    const float* wmW1 = (const float*)d_in[7];
    const float* wmb1 = (const float*)d_in[8];
    const float* wmW2 = (const float*)d_in[9];
    const float* wmb2 = (const float*)d_in[10];
    const float* wmW3 = (const float*)d_in[11];
    const float* wmb3 = (const float*)d_in[12];
    const float* fW1  = (const float*)d_in[13];
    const float* fb1  = (const float*)d_in[14];
    const float* fW2  = (const float*)d_in[15];
    const float* fb2  = (const float*)d_in[16];
    const float* eps  = (const float*)d_in[17];
    const float* g0W1 = (const float*)d_in[18];
    const float* g0b1 = (const float*)d_in[19];
    const float* g0W2 = (const float*)d_in[20];
    const float* g0b2 = (const float*)d_in[21];
    const float* g1W1 = (const float*)d_in[22];
    const float* g1b1 = (const float*)d_in[23];
    const float* g1W2 = (const float*)d_in[24];
    const float* g1b2 = (const float*)d_in[25];
    const float* g2W1 = (const float*)d_in[26];
    const float* g2b1 = (const float*)d_in[27];
    const float* g2W2 = (const float*)d_in[28];
    const float* g2b2 = (const float*)d_in[29];
    const float* outW = (const float*)d_in[30];
    const float* outb = (const float*)d_in[31];
    float* dout = (float*)d_out;

    // dyn smem: max phase = gin<128>: 18448 floats ≈ 73792 B
    static const int SMEM = 73792;
    cudaFuncSetAttribute((const void*)mega_kernel,
        cudaFuncAttributeMaxDynamicSharedMemorySize, SMEM);

    mega_kernel<<<NB, NT, SMEM>>>(X, A, p,
        cW1, cb1, cW2, cb2,
        wmW1, wmb1, wmW2, wmb2, wmW3, wmb3,
        fW1, fb1, fW2, fb2, eps,
        g0W1, g0b1, g0W2, g0b2,
        g1W1, g1b1, g1W2, g1b2,
        g2W1, g2b1, g2W2, g2b2,
        outW, outb, dout, out_size);
}

// round 12
// speedup vs baseline: 1.9904x; 1.0979x over previous
#include <cuda_runtime.h>
#include <math.h>

#define Bx 8
#define Nx 512
#define Dx 128
#define Hx 64
#define FNx 3
#define NLx 3
#define OUTC 10
#define BN (Bx*Nx)
#define NBCAP 128
#define NB 128          // grid size: all blocks co-resident
#define NT 512          // threads per block (16 warps)

// ---------------- device scratch (static, no allocation) ----------------
__device__ float    g_kap[BN];
__device__ float    g_f[FNx][BN];
__device__ float    g_m1;
__device__ unsigned g_adj[BN*16];
__device__ unsigned short g_nbr[BN*NBCAP];
__device__ int      g_ndeg[BN];
__device__ unsigned g_kmask1[Bx*16];
__device__ unsigned g_kmask2[Bx*16];
__device__ float    g_deg[BN];
__device__ float    g_u1[FNx][BN];
__device__ float    g_gamma[FNx][BN];
__device__ float    g_df[FNx][BN];
__device__ float    g_fdf[FNx][BN];
__device__ float    g_rowloss[BN];
__device__ float    g_loss;
__device__ __align__(16) float g_h[NLx][BN*Hx];
__device__ float    g_part[Bx*16*320];
__device__ unsigned g_barcnt[8];            // monotonic across graph replays

// ---------------- software grid barrier (all NB blocks co-resident) -------
__device__ __forceinline__ void gridbar(int id)
{
    __syncthreads();
    __threadfence();
    if (threadIdx.x == 0) {
        unsigned tk = atomicAdd(&g_barcnt[id], 1u);
        unsigned base = tk - (tk & (NB - 1));
        while ((*(volatile unsigned*)&g_barcnt[id]) - base < NB) { }
        __threadfence();
    }
    __syncthreads();
}

// ---------------- gin sub-phase: CSR agg + 2-layer MLP + column partials --
// Register-tiled GEMMs: thread owns 2 cols x 2 nodes; float4 act (broadcast)
// + float2 weights => ~16 FMA per 10 LDS-crossbar cycles.
template<int DIN>
__device__ void gin_phase(float* sm, const float* __restrict__ hin,
    const unsigned* __restrict__ kmask, float eps1,
    const float* __restrict__ W1, const float* __restrict__ b1,
    const float* __restrict__ W2, const float* __restrict__ b2,
    float* __restrict__ hout, int partCol)
{
    float* sW1  = sm;                    // DIN*64
    float* sW2  = sW1 + DIN*64;          // 64*64
    float* sAgg = sW2 + 64*64;           // 32*DIN  (reused as sRed in epilogue)
    float* sHid = sAgg + 32*DIN;         // 32*64
    unsigned* skm = (unsigned*)(sHid + 2048);
    const int tid = threadIdx.x;
    const int nodeBase = blockIdx.x * 32;
    const int b = nodeBase >> 9;
    const int pp = (nodeBase >> 5) & 15;

    for (int i = tid; i < DIN*64/4; i += NT) ((float4*)sW1)[i] = ((const float4*)W1)[i];
    for (int i = tid; i < 64*64/4; i += NT)  ((float4*)sW2)[i] = ((const float4*)W2)[i];
    if (tid < 16) skm[tid] = kmask ? kmask[b*16 + tid] : 0xffffffffu;
    __syncthreads();

    const int w = tid >> 5, lane = tid & 31;

    // aggregation: 16 warps x 2 nodes, vectorized loads
    for (int nn = 0; nn < 2; nn++) {
        int nl = w*2 + nn;
        int node = nodeBase + nl;
        int loc = node & 511;
        bool rk = (skm[loc >> 5] >> (loc & 31)) & 1u;
        if (DIN == 128) {
            float4 acc = make_float4(0.f, 0.f, 0.f, 0.f);
            if (rk) {
                int deg = g_ndeg[node];
                const unsigned short* L = g_nbr + (size_t)node*NBCAP;
                #pragma unroll 4
                for (int n = 0; n < deg; n++) {
                    int j = L[n];
                    if ((skm[j >> 5] >> (j & 31)) & 1u) {
                        float4 v = ((const float4*)(hin + ((size_t)(b*Nx + j))*DIN))[lane];
                        acc.x += v.x; acc.y += v.y; acc.z += v.z; acc.w += v.w;
                    }
                }
            }
            float4 hv = ((const float4*)(hin + (size_t)node*DIN))[lane];
            float4 o;
            o.x = eps1*hv.x + acc.x; o.y = eps1*hv.y + acc.y;
            o.z = eps1*hv.z + acc.z; o.w = eps1*hv.w + acc.w;
            *(float4*)&sAgg[nl*DIN + lane*4] = o;
        } else {
            float2 acc = make_float2(0.f, 0.f);
            if (rk) {
                int deg = g_ndeg[node];
                const unsigned short* L = g_nbr + (size_t)node*NBCAP;
                #pragma unroll 4
                for (int n = 0; n < deg; n++) {
                    int j = L[n];
                    if ((skm[j >> 5] >> (j & 31)) & 1u) {
                        float2 v = ((const float2*)(hin + ((size_t)(b*Nx + j))*DIN))[lane];
                        acc.x += v.x; acc.y += v.y;
                    }
                }
            }
            float2 hv = ((const float2*)(hin + (size_t)node*DIN))[lane];
            float2 o;
            o.x = eps1*hv.x + acc.x; o.y = eps1*hv.y + acc.y;
            *(float2*)&sAgg[nl*DIN + lane*2] = o;
        }
    }
    __syncthreads();

    const int cp = tid & 31, gp = tid >> 5;   // col-pair 0..31, group 0..15

    {   // hidden layer: 2 cols x 2 nodes per thread, float4 over d
        const float4* A0 = (const float4*)(sAgg + gp*DIN);
        const float4* A1 = (const float4*)(sAgg + (gp+16)*DIN);
        float2 bc = *(const float2*)(b1 + 2*cp);
        float r00 = bc.x, r01 = bc.y, r10 = bc.x, r11 = bc.y;
        #pragma unroll 4
        for (int d4 = 0; d4 < DIN/4; d4++) {
            float4 a0 = A0[d4], a1 = A1[d4];
            const float* wd = sW1 + d4*256 + 2*cp;
            float2 w0 = *(const float2*)(wd);
            float2 w1 = *(const float2*)(wd + 64);
            float2 w2 = *(const float2*)(wd + 128);
            float2 w3 = *(const float2*)(wd + 192);
            r00 += a0.x*w0.x + a0.y*w1.x + a0.z*w2.x + a0.w*w3.x;
            r01 += a0.x*w0.y + a0.y*w1.y + a0.z*w2.y + a0.w*w3.y;
            r10 += a1.x*w0.x + a1.y*w1.x + a1.z*w2.x + a1.w*w3.x;
            r11 += a1.x*w0.y + a1.y*w1.y + a1.z*w2.y + a1.w*w3.y;
        }
        *(float2*)(sHid + gp*64 + 2*cp)      = make_float2(fmaxf(r00,0.f), fmaxf(r01,0.f));
        *(float2*)(sHid + (gp+16)*64 + 2*cp) = make_float2(fmaxf(r10,0.f), fmaxf(r11,0.f));
    }
    __syncthreads();

    {   // output layer + fused column partials
        const float4* H0 = (const float4*)(sHid + gp*64);
        const float4* H1 = (const float4*)(sHid + (gp+16)*64);
        float2 bc = *(const float2*)(b2 + 2*cp);
        float r00 = bc.x, r01 = bc.y, r10 = bc.x, r11 = bc.y;
        #pragma unroll 4
        for (int d4 = 0; d4 < 16; d4++) {
            float4 a0 = H0[d4], a1 = H1[d4];
            const float* wd = sW2 + d4*256 + 2*cp;
            float2 w0 = *(const float2*)(wd);
            float2 w1 = *(const float2*)(wd + 64);
            float2 w2 = *(const float2*)(wd + 128);
            float2 w3 = *(const float2*)(wd + 192);
            r00 += a0.x*w0.x + a0.y*w1.x + a0.z*w2.x + a0.w*w3.x;
            r01 += a0.x*w0.y + a0.y*w1.y + a0.z*w2.y + a0.w*w3.y;
            r10 += a1.x*w0.x + a1.y*w1.x + a1.z*w2.x + a1.w*w3.x;
            r11 += a1.x*w0.y + a1.y*w1.y + a1.z*w2.y + a1.w*w3.y;
        }
        float p0x = fmaxf(r00,0.f), p0y = fmaxf(r01,0.f);
        float p1x = fmaxf(r10,0.f), p1y = fmaxf(r11,0.f);
        if (hout) {
            *(float2*)(hout + ((size_t)(nodeBase + gp))*64 + 2*cp)    = make_float2(p0x, p0y);
            *(float2*)(hout + ((size_t)(nodeBase + gp+16))*64 + 2*cp) = make_float2(p1x, p1y);
        }
        __syncthreads();   // sHid reads done before sAgg reuse is safe anyway; order partials
        *(float2*)(sAgg + gp*64 + 2*cp) = make_float2(p0x + p1x, p0y + p1y);
    }
    __syncthreads();
    if (tid < 64) {
        float s = 0.f;
        #pragma unroll
        for (int g = 0; g < 16; g++) s += sAgg[g*64 + tid];
        g_part[(b*16 + pp)*320 + partCol + tid] = s;
    }
    __syncthreads();
}

// ---------------- the megakernel ------------------------------------------
__global__ __launch_bounds__(NT, 1)
void mega_kernel(const float* __restrict__ X, const float* __restrict__ A,
    const int* __restrict__ p_ptr,
    const float* __restrict__ cW1, const float* __restrict__ cb1,
    const float* __restrict__ cW2, const float* __restrict__ cb2,
    const float* __restrict__ wmW1, const float* __restrict__ wmb1,
    const float* __restrict__ wmW2, const float* __restrict__ wmb2,
    const float* __restrict__ wmW3, const float* __restrict__ wmb3,
    const float* __restrict__ fW1, const float* __restrict__ fb1,
    const float* __restrict__ fW2, const float* __restrict__ fb2,
    const float* __restrict__ eps,
    const float* __restrict__ g0W1, const float* __restrict__ g0b1,
    const float* __restrict__ g0W2, const float* __restrict__ g0b2,
    const float* __restrict__ g1W1, const float* __restrict__ g1b1,
    const float* __restrict__ g1W2, const float* __restrict__ g1b2,
    const float* __restrict__ g2W1, const float* __restrict__ g2b1,
    const float* __restrict__ g2W2, const float* __restrict__ g2b2,
    const float* __restrict__ outW, const float* __restrict__ outb,
    float* __restrict__ dout, int out_size)
{
    extern __shared__ float sm[];
    __shared__ int wcnt[16];
    const int tid = threadIdx.x, bid = blockIdx.x;
    const int w = tid >> 5, lane = tid & 31;
    const unsigned full = 0xffffffffu;

    // ================= PHASE 1a: adjacency compress + CSR (vectorized) ====
    {
        int warpG = bid*16 + w;              // 0..2047
        for (int k = 0; k < 2; k++) {
            int r = warpG*2 + k;
            const float4* Ar4 = (const float4*)(A + (size_t)r * Nx);
            unsigned wreg[4];
            #pragma unroll
            for (int g = 0; g < 4; g++) {
                float4 v = Ar4[g*32 + lane];
                unsigned nib = (unsigned)(v.x != 0.f)
                             | ((unsigned)(v.y != 0.f) << 1)
                             | ((unsigned)(v.z != 0.f) << 2)
                             | ((unsigned)(v.w != 0.f) << 3);
                unsigned wd = nib << (4*(lane & 7));
                wd |= __shfl_xor_sync(full, wd, 1);
                wd |= __shfl_xor_sync(full, wd, 2);
                wd |= __shfl_xor_sync(full, wd, 4);
                wreg[g] = wd;                // holds word index g*4 + (lane>>3)
            }
            unsigned srcl = (lane & 3) * 8;
            unsigned q0 = __shfl_sync(full, wreg[0], srcl);
            unsigned q1 = __shfl_sync(full, wreg[1], srcl);
            unsigned q2 = __shfl_sync(full, wreg[2], srcl);
            unsigned q3 = __shfl_sync(full, wreg[3], srcl);
            int g2 = lane >> 2;
            unsigned myword = (g2 == 0) ? q0 : (g2 == 1) ? q1 : (g2 == 2) ? q2 : q3;
            if (lane < 16) g_adj[(size_t)r*16 + lane] = myword;
            unsigned wv = (lane < 16) ? myword : 0u;
            int cnt = __popc(wv);
            int ex = cnt;
            #pragma unroll
            for (int o = 1; o < 32; o <<= 1) {
                int nv = __shfl_up_sync(full, ex, o);
                if (lane >= o) ex += nv;
            }
            int total = __shfl_sync(full, ex, 15);
            ex -= cnt;
            if (lane < 16) {
                int pos = ex;
                unsigned bits = wv;
                while (bits) {
                    int j = __ffs(bits) - 1; bits &= bits - 1;
                    if (pos < NBCAP)
                        g_nbr[(size_t)r*NBCAP + pos] = (unsigned short)(lane*32 + j);
                    pos++;
                }
            }
            if (lane == 0) g_ndeg[r] = (total < NBCAP) ? total : NBCAP;
        }
    }

    // ================= PHASE 1b: node MLPs + X column partials ============
    {
        float* sX    = sm;                  // 32*128 = 4096
        float* sW1s  = sm + 4096;           // 128*64 = 8192
        float* sHid  = sm + 4096 + 8192;    // 32*64  = 2048
        float* sW2v  = sHid + 2048;         // 64
        float* sPartX= sm + 14400;          // 512
        int nodeBase = bid * 32;
        int b = bid >> 4, pp = bid & 15;
        __syncthreads();
        for (int i = tid; i < 32*Dx/4; i += NT)
            ((float4*)sX)[i] = ((const float4*)(X + (size_t)nodeBase*Dx))[i];
        __syncthreads();

        // X column partials for readout (cols 0..127)
        {
            int qtr = tid >> 7, col = tid & 127;
            float s = 0.f;
            #pragma unroll
            for (int n = 0; n < 8; n++) s += sX[(qtr*8 + n)*Dx + col];
            sPartX[qtr*128 + col] = s;
        }
        __syncthreads();
        if (tid < 128) {
            float s = sPartX[tid] + sPartX[128+tid] + sPartX[256+tid] + sPartX[384+tid];
            g_part[(b*16 + pp)*320 + tid] = s;
        }

        const int cp = tid & 31, gp = tid >> 5;
        for (int m = 0; m < 4; m++) {
            const float* W1 = (m == 0) ? cW1 : fW1 + (size_t)(m-1)*Dx*Hx;
            const float* B1 = (m == 0) ? cb1 : fb1 + (m-1)*Hx;
            const float* W2 = (m == 0) ? cW2 : fW2 + (m-1)*Hx;
            float B2 = (m == 0) ? cb2[0] : fb2[m-1];
            __syncthreads();
            for (int i = tid; i < Dx*Hx/4; i += NT)
                ((float4*)sW1s)[i] = ((const float4*)W1)[i];
            if (tid < 64) sW2v[tid] = W2[tid];
            __syncthreads();
            {   // hidden: 2 cols x 2 nodes per thread, float4 over d
                const float4* A0 = (const float4*)(sX + gp*Dx);
                const float4* A1 = (const float4*)(sX + (gp+16)*Dx);
                float2 bc = *(const float2*)(B1 + 2*cp);
                float r00 = bc.x, r01 = bc.y, r10 = bc.x, r11 = bc.y;
                #pragma unroll 4
                for (int d4 = 0; d4 < Dx/4; d4++) {
                    float4 a0 = A0[d4], a1 = A1[d4];
                    const float* wd = sW1s + d4*256 + 2*cp;
                    float2 w0 = *(const float2*)(wd);
                    float2 w1 = *(const float2*)(wd + 64);
                    float2 w2 = *(const float2*)(wd + 128);
                    float2 w3 = *(const float2*)(wd + 192);
                    r00 += a0.x*w0.x + a0.y*w1.x + a0.z*w2.x + a0.w*w3.x;
                    r01 += a0.x*w0.y + a0.y*w1.y + a0.z*w2.y + a0.w*w3.y;
                    r10 += a1.x*w0.x + a1.y*w1.x + a1.z*w2.x + a1.w*w3.x;
                    r11 += a1.x*w0.y + a1.y*w1.y + a1.z*w2.y + a1.w*w3.y;
                }
                *(float2*)(sHid + gp*64 + 2*cp)      = make_float2(fmaxf(r00,0.f), fmaxf(r01,0.f));
                *(float2*)(sHid + (gp+16)*64 + 2*cp) = make_float2(fmaxf(r10,0.f), fmaxf(r11,0.f));
            }
            __syncthreads();
            // scalar head: warp per node, 2 rounds
            for (int nn = 0; nn < 2; nn++) {
                int nl = w*2 + nn;
                float v = sHid[nl*64 + lane] * sW2v[lane]
                        + sHid[nl*64 + 32 + lane] * sW2v[32 + lane];
                #pragma unroll
                for (int o = 16; o > 0; o >>= 1) v += __shfl_xor_sync(full, v, o);
                if (lane == 0) {
                    float sig = 1.f / (1.f + expf(-(v + B2)));
                    int node = nodeBase + nl;
                    if (m == 0) g_kap[node] = sig; else g_f[m-1][node] = sig;
                }
            }
        }
        if (bid == 0) {   // scalar m1 = sigmoid(MLP(1))
            float* s1 = sm + 15000;
            float* s2 = s1 + 64;
            __syncthreads();
            if (tid < 64) s1[tid] = fmaxf(wmW1[tid] + wmb1[tid], 0.f);
            __syncthreads();
            if (tid < 32) {
                float a = wmb2[tid];
                #pragma unroll
                for (int i = 0; i < 64; i++) a += s1[i] * wmW2[i*32 + tid];
                s2[tid] = fmaxf(a, 0.f);
            }
            __syncthreads();
            if (tid == 0) {
                float s = wmb3[0];
                #pragma unroll
                for (int i = 0; i < 32; i++) s += s2[i] * wmW3[i];
                g_m1 = 1.f / (1.f + expf(-s));
            }
        }
    }

    gridbar(0);   // kap/f/m1/adj ready

    // ================= PHASE 2: prune (blocks 0-7) + curv1 + gin0 =========
    if (bid < Bx) {   // prune batch b = bid; 1 element per thread
        int b = bid;
        float* sv = sm;         // 512
        float* so = sm + 512;   // 512
        float v = g_kap[b*Nx + tid];
        sv[tid] = v; so[tid] = v;
        __syncthreads();
        for (int k = 2; k <= Nx; k <<= 1)
            for (int j = k >> 1; j > 0; j >>= 1) {
                int ixj = tid ^ j;
                if (ixj > tid) {
                    float a = sv[tid], c = sv[ixj];
                    bool up = ((tid & k) == 0);
                    if ((a > c) == up) { sv[tid] = c; sv[ixj] = a; }
                }
                __syncthreads();
            }
        int p = *p_ptr;
        float keepA = 1.f, keepB = 1.f;
        for (int phase = 0; phase < 2; phase++) {
            int kk = (Nx * p * (phase+1)) / 100;
            bool removed = false;
            if (kk >= 1) {
                float T = sv[Nx - kk];
                int cgt = __syncthreads_count(so[tid] > T);
                int need = kk - cgt;
                removed = (so[tid] > T);
                bool eq = (so[tid] == T) && (need > 0);
                unsigned bal = __ballot_sync(full, eq);
                if (lane == 0) wcnt[w] = __popc(bal);
                __syncthreads();
                int off = 0;
                #pragma unroll
                for (int i = 0; i < 16; i++) if (i < w) off += wcnt[i];
                int rank = off + __popc(bal & ((1u << lane) - 1u));
                if (eq && rank < need) removed = true;
            }
            if (phase == 0) keepA = removed ? 0.f : 1.f;
            else           keepB = removed ? 0.f : 1.f;
            __syncthreads();
        }
        unsigned mA = __ballot_sync(full, keepA != 0.f);
        unsigned mB = __ballot_sync(full, keepA * keepB != 0.f);
        if (lane == 0) { g_kmask1[b*16 + w] = mA; g_kmask2[b*16 + w] = mB; }
        __syncthreads();
    }

    {   // curv pass 1: batch = bid>>4, 32 rows/block, 2 rows/warp
        int b2 = bid >> 4;
        int rowbase = (bid & 15) * 32;
        __syncthreads();
        for (int i = tid; i < FNx*Nx; i += NT)
            sm[i] = g_f[i >> 9][b2*Nx + (i & 511)];
        __syncthreads();
        float m1 = g_m1;
        unsigned myw[2];
        #pragma unroll
        for (int k = 0; k < 2; k++) {
            int row = rowbase + w*2 + k;
            myw[k] = (lane < 16) ? g_adj[(size_t)(b2*Nx + row)*16 + lane] : 0u;
        }
        int degi[2];
        #pragma unroll
        for (int k = 0; k < 2; k++) degi[k] = __popc(myw[k]);
        float u1[2][FNx], u2[2][FNx];
        #pragma unroll
        for (int k = 0; k < 2; k++)
            #pragma unroll
            for (int i = 0; i < FNx; i++) { u1[k][i] = 0.f; u2[k][i] = 0.f; }
        #pragma unroll
        for (int c = 0; c < 16; c++) {
            float fv[FNx];
            #pragma unroll
            for (int i = 0; i < FNx; i++) fv[i] = sm[i*512 + c*32 + lane];
            #pragma unroll
            for (int k = 0; k < 2; k++) {
                unsigned bits = __shfl_sync(full, myw[k], c);
                float sel = (float)((bits >> lane) & 1u);
                #pragma unroll
                for (int i = 0; i < FNx; i++) {
                    u1[k][i] += sel * fv[i];
                    u2[k][i] += sel * fv[i] * fv[i];
                }
            }
        }
        #pragma unroll
        for (int o = 16; o > 0; o >>= 1) {
            #pragma unroll
            for (int k = 0; k < 2; k++) {
                degi[k] += __shfl_xor_sync(full, degi[k], o);
                #pragma unroll
                for (int i = 0; i < FNx; i++) {
                    u1[k][i] += __shfl_xor_sync(full, u1[k][i], o);
                    u2[k][i] += __shfl_xor_sync(full, u2[k][i], o);
                }
            }
        }
        if (lane == 0) {
            #pragma unroll
            for (int k = 0; k < 2; k++) {
                int row = rowbase + w*2 + k;
                int idx = b2*Nx + row;
                float deg = (float)degi[k];
                g_deg[idx] = deg;
                #pragma unroll
                for (int i = 0; i < FNx; i++) {
                    float fr = sm[i*512 + row];
                    g_u1[i][idx] = u1[k][i];
                    float gam = 0.5f*m1*(fr*fr*deg - 2.f*fr*u1[k][i] + u2[k][i]);
                    float df  = m1*(fr*deg - u1[k][i]);
                    g_gamma[i][idx] = gam; g_df[i][idx] = df; g_fdf[i][idx] = fr*df;
                }
            }
        }
        __syncthreads();
    }

    {   // gin layer 0 (partials -> cols 128..191)
        float eps1 = 1.f + eps[0];
        gin_phase<128>(sm, X, nullptr, eps1, g0W1, g0b1, g0W2, g0b2, &g_h[0][0], 128);
    }

    gridbar(1);   // gamma/df/fdf, kmask1, h0 ready

    // ================= PHASE 3: curv2 + gin1 ==============================
    {   // curv pass 2
        int b2 = bid >> 4;
        int rowbase = (bid & 15) * 32;
        float* sgam = sm;            // 3*512
        float* sdf  = sm + 1536;
        float* sfd  = sm + 3072;
        for (int i = tid; i < FNx*Nx; i += NT) {
            int f = i >> 9, j = i & 511, id2 = b2*Nx + j;
            sgam[f*512 + j] = g_gamma[f][id2];
            sdf[f*512 + j]  = g_df[f][id2];
            sfd[f*512 + j]  = g_fdf[f][id2];
        }
        __syncthreads();
        float m1 = g_m1;
        unsigned myw[2];
        #pragma unroll
        for (int k = 0; k < 2; k++) {
            int row = rowbase + w*2 + k;
            myw[k] = (lane < 16) ? g_adj[(size_t)(b2*Nx + row)*16 + lane] : 0u;
        }
        float v1[2][FNx], v2[2][FNx], v3[2][FNx];
        #pragma unroll
        for (int k = 0; k < 2; k++)
            #pragma unroll
            for (int i = 0; i < FNx; i++) { v1[k][i]=0.f; v2[k][i]=0.f; v3[k][i]=0.f; }
        #pragma unroll
        for (int c = 0; c < 16; c++) {
            int j = c*32 + lane;
            float gv[FNx], dv[FNx], fv[FNx];
            #pragma unroll
            for (int i = 0; i < FNx; i++) {
                gv[i] = sgam[i*512 + j]; dv[i] = sdf[i*512 + j]; fv[i] = sfd[i*512 + j];
            }
            #pragma unroll
            for (int k = 0; k < 2; k++) {
                unsigned bits = __shfl_sync(full, myw[k], c);
                float sel = (float)((bits >> lane) & 1u);
                #pragma unroll
                for (int i = 0; i < FNx; i++) {
                    v1[k][i] += sel * gv[i];
                    v2[k][i] += sel * dv[i];
                    v3[k][i] += sel * fv[i];
                }
            }
        }
        #pragma unroll
        for (int o = 16; o > 0; o >>= 1) {
            #pragma unroll
            for (int k = 0; k < 2; k++)
                #pragma unroll
                for (int i = 0; i < FNx; i++) {
                    v1[k][i] += __shfl_xor_sync(full, v1[k][i], o);
                    v2[k][i] += __shfl_xor_sync(full, v2[k][i], o);
                    v3[k][i] += __shfl_xor_sync(full, v3[k][i], o);
                }
        }
        if (lane == 0) {
            #pragma unroll
            for (int k = 0; k < 2; k++) {
                int row = rowbase + w*2 + k;
                int idx = b2*Nx + row;
                float deg = g_deg[idx], kap = g_kap[idx];
                float term = 0.f;
                #pragma unroll
                for (int i = 0; i < FNx; i++) {
                    float gam = sgam[i*512 + row], df = sdf[i*512 + row], fdf = sfd[i*512 + row];
                    float fr = g_f[i][idx];
                    float u1v = g_u1[i][idx];
                    float dgam = m1*(gam*deg - v1[k][i]);
                    float gfd  = 0.5f*m1*(fdf*deg - fr*v2[k][i] - df*u1v + v3[k][i]);
                    float g2 = 0.5f*dgam - gfd;
                    term += fmaxf(kap*gam - g2, 0.f);
                }
                g_rowloss[idx] = term - 3.f*kap;
            }
        }
        __syncthreads();
    }
    {   // gin layer 1 (partials -> cols 192..255)
        float eps1 = 1.f + eps[1];
        gin_phase<64>(sm, &g_h[0][0], g_kmask1, eps1, g1W1, g1b1, g1W2, g1b2, &g_h[1][0], 192);
    }

    gridbar(2);   // h1, rowloss ready

    // ================= PHASE 4: gin2 (no h write) + loss reduce ===========
    {
        float eps1 = 1.f + eps[2];
        gin_phase<64>(sm, &g_h[1][0], g_kmask2, eps1, g2W1, g2b1, g2W2, g2b2, nullptr, 256);
    }
    if (bid == NB-1) {   // loss reduction (rowloss ready since gridbar(2))
        float lp = 0.f;
        #pragma unroll
        for (int i = tid; i < BN; i += NT) lp += g_rowloss[i];
        float* L = sm;
        L[tid] = lp;
        __syncthreads();
        for (int o = 256; o > 0; o >>= 1) { if (tid < o) L[tid] += L[tid + o]; __syncthreads(); }
        if (tid == 0) g_loss = L[0];
    }

    gridbar(3);   // all partials + loss ready

    // ================= PHASE 5: final output GEMM =========================
    if (bid < Bx) {
        int b = bid;
        float* S = sm;
        if (tid < 320) {
            float a = 0.f;
            #pragma unroll
            for (int p2 = 0; p2 < 16; p2++) a += g_part[(b*16 + p2)*320 + tid];
            S[tid] = a;
        }
        __syncthreads();
        if (w < OUTC) {   // warp per output column
            float acc = 0.f;
            for (int f = lane; f < 320; f += 32) acc += S[f] * outW[f*OUTC + w];
            #pragma unroll
            for (int o = 16; o > 0; o >>= 1) acc += __shfl_xor_sync(full, acc, o);
            if (lane == 0) dout[b*OUTC + w] = acc + outb[w];
        }
        if (b == 0 && tid == 320 && out_size > Bx*OUTC) dout[Bx*OUTC] = g_loss;
    }
}

// ---------------- launch ----------------
extern "C" void kernel_launch(void* const* d_in, const int* in_sizes, int n_in,
                              void* d_out, int out_size) {
    const float* X    = (const float*)d_in[0];
    const float* A    = (const float*)d_in[1];
    const int*   p    = (const int*)  d_in[2];
    const float* cW1  = (const float*)d_in[3];
    const float* cb1  = (const float*)d_in[4];
    const float* cW2  = (const float*)d_in[5];
    const float* cb2  = (const float*)d_in[6];
    const float* wmW1 = (const float*)d_in[7];
    const float* wmb1 = (const float*)d_in[8];
    const float* wmW2 = (const float*)d_in[9];
    const float* wmb2 = (const float*)d_in[10];
    const float* wmW3 = (const float*)d_in[11];
    const float* wmb3 = (const float*)d_in[12];
    const float* fW1  = (const float*)d_in[13];
    const float* fb1  = (const float*)d_in[14];
    const float* fW2  = (const float*)d_in[15];
    const float* fb2  = (const float*)d_in[16];
    const float* eps  = (const float*)d_in[17];
    const float* g0W1 = (const float*)d_in[18];
    const float* g0b1 = (const float*)d_in[19];
    const float* g0W2 = (const float*)d_in[20];
    const float* g0b2 = (const float*)d_in[21];
    const float* g1W1 = (const float*)d_in[22];
    const float* g1b1 = (const float*)d_in[23];
    const float* g1W2 = (const float*)d_in[24];
    const float* g1b2 = (const float*)d_in[25];
    const float* g2W1 = (const float*)d_in[26];
    const float* g2b1 = (const float*)d_in[27];
    const float* g2W2 = (const float*)d_in[28];
    const float* g2b2 = (const float*)d_in[29];
    const float* outW = (const float*)d_in[30];
    const float* outb = (const float*)d_in[31];
    float* dout = (float*)d_out;

    // dyn smem: max phase = gin<128>: 18448 floats ≈ 73792 B
    static const int SMEM = 73792;
    cudaFuncSetAttribute((const void*)mega_kernel,
        cudaFuncAttributeMaxDynamicSharedMemorySize, SMEM);

    mega_kernel<<<NB, NT, SMEM>>>(X, A, p,
        cW1, cb1, cW2, cb2,
        wmW1, wmb1, wmW2, wmb2, wmW3, wmb3,
        fW1, fb1, fW2, fb2, eps,
        g0W1, g0b1, g0W2, g0b2,
        g1W1, g1b1, g1W2, g1b2,
        g2W1, g2b1, g2W2, g2b2,
        outW, outb, dout, out_size);
}

// round 14
// speedup vs baseline: 1.9971x; 1.0034x over previous
#include <cuda_runtime.h>
#include <math.h>

#define Bx 8
#define Nx 512
#define Dx 128
#define Hx 64
#define FNx 3
#define NLx 3
#define OUTC 10
#define BN (Bx*Nx)
#define NBCAP 128
#define NB 128          // grid size: all blocks co-resident
#define NT 512          // threads per block (16 warps)

// ---------------- device scratch (static, no allocation) ----------------
__device__ float    g_kap[BN];
__device__ float    g_f[FNx][BN];
__device__ float    g_m1;
__device__ unsigned g_adj[BN*16];
__device__ unsigned short g_nbr[BN*NBCAP];
__device__ int      g_ndeg[BN];
__device__ unsigned g_kmask1[Bx*16];
__device__ unsigned g_kmask2[Bx*16];
__device__ float    g_deg[BN];
__device__ float    g_u1[FNx][BN];
__device__ float    g_gamma[FNx][BN];
__device__ float    g_df[FNx][BN];
__device__ float    g_fdf[FNx][BN];
__device__ float    g_rowloss[BN];
__device__ float    g_loss;
__device__ __align__(16) float g_h[NLx][BN*Hx];
__device__ float    g_part[Bx*16*320];
__device__ unsigned g_barcnt[8];            // monotonic across graph replays

// ---------------- software grid barrier (all NB blocks co-resident) -------
__device__ __forceinline__ void gridbar(int id)
{
    __syncthreads();
    __threadfence();
    if (threadIdx.x == 0) {
        unsigned tk = atomicAdd(&g_barcnt[id], 1u);
        unsigned base = tk - (tk & (NB - 1));
        while ((*(volatile unsigned*)&g_barcnt[id]) - base < NB) { }
        __threadfence();
    }
    __syncthreads();
}

// ---------------- gin sub-phase: CSR agg + 2-layer MLP + column partials --
// Register-tiled GEMMs: thread owns 2 cols x 2 nodes; float4 act (broadcast)
// + float2 weights => ~16 FMA per 10 LDS-crossbar cycles.
template<int DIN>
__device__ void gin_phase(float* sm, const float* __restrict__ hin,
    const unsigned* __restrict__ kmask, float eps1,
    const float* __restrict__ W1, const float* __restrict__ b1,
    const float* __restrict__ W2, const float* __restrict__ b2,
    float* __restrict__ hout, int partCol)
{
    float* sW1  = sm;                    // DIN*64
    float* sW2  = sW1 + DIN*64;          // 64*64
    float* sAgg = sW2 + 64*64;           // 32*DIN  (reused as sRed in epilogue)
    float* sHid = sAgg + 32*DIN;         // 32*64
    unsigned* skm = (unsigned*)(sHid + 2048);
    const int tid = threadIdx.x;
    const int nodeBase = blockIdx.x * 32;
    const int b = nodeBase >> 9;
    const int pp = (nodeBase >> 5) & 15;

    for (int i = tid; i < DIN*64/4; i += NT) ((float4*)sW1)[i] = ((const float4*)W1)[i];
    for (int i = tid; i < 64*64/4; i += NT)  ((float4*)sW2)[i] = ((const float4*)W2)[i];
    if (tid < 16) skm[tid] = kmask ? kmask[b*16 + tid] : 0xffffffffu;
    __syncthreads();

    const int w = tid >> 5, lane = tid & 31;

    // aggregation: 16 warps x 2 nodes, vectorized loads
    for (int nn = 0; nn < 2; nn++) {
        int nl = w*2 + nn;
        int node = nodeBase + nl;
        int loc = node & 511;
        bool rk = (skm[loc >> 5] >> (loc & 31)) & 1u;
        if (DIN == 128) {
            float4 acc = make_float4(0.f, 0.f, 0.f, 0.f);
            if (rk) {
                int deg = g_ndeg[node];
                const unsigned short* L = g_nbr + (size_t)node*NBCAP;
                #pragma unroll 4
                for (int n = 0; n < deg; n++) {
                    int j = L[n];
                    if ((skm[j >> 5] >> (j & 31)) & 1u) {
                        float4 v = ((const float4*)(hin + ((size_t)(b*Nx + j))*DIN))[lane];
                        acc.x += v.x; acc.y += v.y; acc.z += v.z; acc.w += v.w;
                    }
                }
            }
            float4 hv = ((const float4*)(hin + (size_t)node*DIN))[lane];
            float4 o;
            o.x = eps1*hv.x + acc.x; o.y = eps1*hv.y + acc.y;
            o.z = eps1*hv.z + acc.z; o.w = eps1*hv.w + acc.w;
            *(float4*)&sAgg[nl*DIN + lane*4] = o;
        } else {
            float2 acc = make_float2(0.f, 0.f);
            if (rk) {
                int deg = g_ndeg[node];
                const unsigned short* L = g_nbr + (size_t)node*NBCAP;
                #pragma unroll 4
                for (int n = 0; n < deg; n++) {
                    int j = L[n];
                    if ((skm[j >> 5] >> (j & 31)) & 1u) {
                        float2 v = ((const float2*)(hin + ((size_t)(b*Nx + j))*DIN))[lane];
                        acc.x += v.x; acc.y += v.y;
                    }
                }
            }
            float2 hv = ((const float2*)(hin + (size_t)node*DIN))[lane];
            float2 o;
            o.x = eps1*hv.x + acc.x; o.y = eps1*hv.y + acc.y;
            *(float2*)&sAgg[nl*DIN + lane*2] = o;
        }
    }
    __syncthreads();

    const int cp = tid & 31, gp = tid >> 5;   // col-pair 0..31, group 0..15

    {   // hidden layer: 2 cols x 2 nodes per thread, float4 over d
        const float4* A0 = (const float4*)(sAgg + gp*DIN);
        const float4* A1 = (const float4*)(sAgg + (gp+16)*DIN);
        float2 bc = *(const float2*)(b1 + 2*cp);
        float r00 = bc.x, r01 = bc.y, r10 = bc.x, r11 = bc.y;
        #pragma unroll 4
        for (int d4 = 0; d4 < DIN/4; d4++) {
            float4 a0 = A0[d4], a1 = A1[d4];
            const float* wd = sW1 + d4*256 + 2*cp;
            float2 w0 = *(const float2*)(wd);
            float2 w1 = *(const float2*)(wd + 64);
            float2 w2 = *(const float2*)(wd + 128);
            float2 w3 = *(const float2*)(wd + 192);
            r00 += a0.x*w0.x + a0.y*w1.x + a0.z*w2.x + a0.w*w3.x;
            r01 += a0.x*w0.y + a0.y*w1.y + a0.z*w2.y + a0.w*w3.y;
            r10 += a1.x*w0.x + a1.y*w1.x + a1.z*w2.x + a1.w*w3.x;
            r11 += a1.x*w0.y + a1.y*w1.y + a1.z*w2.y + a1.w*w3.y;
        }
        *(float2*)(sHid + gp*64 + 2*cp)      = make_float2(fmaxf(r00,0.f), fmaxf(r01,0.f));
        *(float2*)(sHid + (gp+16)*64 + 2*cp) = make_float2(fmaxf(r10,0.f), fmaxf(r11,0.f));
    }
    __syncthreads();

    {   // output layer + fused column partials
        const float4* H0 = (const float4*)(sHid + gp*64);
        const float4* H1 = (const float4*)(sHid + (gp+16)*64);
        float2 bc = *(const float2*)(b2 + 2*cp);
        float r00 = bc.x, r01 = bc.y, r10 = bc.x, r11 = bc.y;
        #pragma unroll 4
        for (int d4 = 0; d4 < 16; d4++) {
            float4 a0 = H0[d4], a1 = H1[d4];
            const float* wd = sW2 + d4*256 + 2*cp;
            float2 w0 = *(const float2*)(wd);
            float2 w1 = *(const float2*)(wd + 64);
            float2 w2 = *(const float2*)(wd + 128);
            float2 w3 = *(const float2*)(wd + 192);
            r00 += a0.x*w0.x + a0.y*w1.x + a0.z*w2.x + a0.w*w3.x;
            r01 += a0.x*w0.y + a0.y*w1.y + a0.z*w2.y + a0.w*w3.y;
            r10 += a1.x*w0.x + a1.y*w1.x + a1.z*w2.x + a1.w*w3.x;
            r11 += a1.x*w0.y + a1.y*w1.y + a1.z*w2.y + a1.w*w3.y;
        }
        float p0x = fmaxf(r00,0.f), p0y = fmaxf(r01,0.f);
        float p1x = fmaxf(r10,0.f), p1y = fmaxf(r11,0.f);
        if (hout) {
            *(float2*)(hout + ((size_t)(nodeBase + gp))*64 + 2*cp)    = make_float2(p0x, p0y);
            *(float2*)(hout + ((size_t)(nodeBase + gp+16))*64 + 2*cp) = make_float2(p1x, p1y);
        }
        __syncthreads();   // sHid reads done before sAgg reuse is safe anyway; order partials
        *(float2*)(sAgg + gp*64 + 2*cp) = make_float2(p0x + p1x, p0y + p1y);
    }
    __syncthreads();
    if (tid < 64) {
        float s = 0.f;
        #pragma unroll
        for (int g = 0; g < 16; g++) s += sAgg[g*64 + tid];
        g_part[(b*16 + pp)*320 + partCol + tid] = s;
    }
    __syncthreads();
}

// ---------------- the megakernel ------------------------------------------
__global__ __launch_bounds__(NT, 1)
void mega_kernel(const float* __restrict__ X, const float* __restrict__ A,
    const int* __restrict__ p_ptr,
    const float* __restrict__ cW1, const float* __restrict__ cb1,
    const float* __restrict__ cW2, const float* __restrict__ cb2,
    const float* __restrict__ wmW1, const float* __restrict__ wmb1,
    const float* __restrict__ wmW2, const float* __restrict__ wmb2,
    const float* __restrict__ wmW3, const float* __restrict__ wmb3,
    const float* __restrict__ fW1, const float* __restrict__ fb1,
    const float* __restrict__ fW2, const float* __restrict__ fb2,
    const float* __restrict__ eps,
    const float* __restrict__ g0W1, const float* __restrict__ g0b1,
    const float* __restrict__ g0W2, const float* __restrict__ g0b2,
    const float* __restrict__ g1W1, const float* __restrict__ g1b1,
    const float* __restrict__ g1W2, const float* __restrict__ g1b2,
    const float* __restrict__ g2W1, const float* __restrict__ g2b1,
    const float* __restrict__ g2W2, const float* __restrict__ g2b2,
    const float* __restrict__ outW, const float* __restrict__ outb,
    float* __restrict__ dout, int out_size)
{
    extern __shared__ float sm[];
    __shared__ int wcnt[16];
    const int tid = threadIdx.x, bid = blockIdx.x;
    const int w = tid >> 5, lane = tid & 31;
    const unsigned full = 0xffffffffu;

    // ================= PHASE 1a: adjacency compress + CSR (vectorized) ====
    {
        int warpG = bid*16 + w;              // 0..2047
        for (int k = 0; k < 2; k++) {
            int r = warpG*2 + k;
            const float4* Ar4 = (const float4*)(A + (size_t)r * Nx);
            unsigned wreg[4];
            #pragma unroll
            for (int g = 0; g < 4; g++) {
                float4 v = Ar4[g*32 + lane];
                unsigned nib = (unsigned)(v.x != 0.f)
                             | ((unsigned)(v.y != 0.f) << 1)
                             | ((unsigned)(v.z != 0.f) << 2)
                             | ((unsigned)(v.w != 0.f) << 3);
                unsigned wd = nib << (4*(lane & 7));
                wd |= __shfl_xor_sync(full, wd, 1);
                wd |= __shfl_xor_sync(full, wd, 2);
                wd |= __shfl_xor_sync(full, wd, 4);
                wreg[g] = wd;                // holds word index g*4 + (lane>>3)
            }
            unsigned srcl = (lane & 3) * 8;
            unsigned q0 = __shfl_sync(full, wreg[0], srcl);
            unsigned q1 = __shfl_sync(full, wreg[1], srcl);
            unsigned q2 = __shfl_sync(full, wreg[2], srcl);
            unsigned q3 = __shfl_sync(full, wreg[3], srcl);
            int g2 = lane >> 2;
            unsigned myword = (g2 == 0) ? q0 : (g2 == 1) ? q1 : (g2 == 2) ? q2 : q3;
            if (lane < 16) g_adj[(size_t)r*16 + lane] = myword;
            unsigned wv = (lane < 16) ? myword : 0u;
            int cnt = __popc(wv);
            int ex = cnt;
            #pragma unroll
            for (int o = 1; o < 32; o <<= 1) {
                int nv = __shfl_up_sync(full, ex, o);
                if (lane >= o) ex += nv;
            }
            int total = __shfl_sync(full, ex, 15);
            ex -= cnt;
            if (lane < 16) {
                int pos = ex;
                unsigned bits = wv;
                while (bits) {
                    int j = __ffs(bits) - 1; bits &= bits - 1;
                    if (pos < NBCAP)
                        g_nbr[(size_t)r*NBCAP + pos] = (unsigned short)(lane*32 + j);
                    pos++;
                }
            }
            if (lane == 0) g_ndeg[r] = (total < NBCAP) ? total : NBCAP;
        }
    }

    // ================= PHASE 1b: node MLPs + X column partials ============
    {
        float* sX    = sm;                  // 32*128 = 4096
        float* sW1s  = sm + 4096;           // 128*64 = 8192
        float* sHid  = sm + 4096 + 8192;    // 32*64  = 2048
        float* sW2v  = sHid + 2048;         // 64
        float* sPartX= sm + 14400;          // 512
        int nodeBase = bid * 32;
        int b = bid >> 4, pp = bid & 15;
        __syncthreads();
        for (int i = tid; i < 32*Dx/4; i += NT)
            ((float4*)sX)[i] = ((const float4*)(X + (size_t)nodeBase*Dx))[i];
        __syncthreads();

        // X column partials for readout (cols 0..127)
        {
            int qtr = tid >> 7, col = tid & 127;
            float s = 0.f;
            #pragma unroll
            for (int n = 0; n < 8; n++) s += sX[(qtr*8 + n)*Dx + col];
            sPartX[qtr*128 + col] = s;
        }
        __syncthreads();
        if (tid < 128) {
            float s = sPartX[tid] + sPartX[128+tid] + sPartX[256+tid] + sPartX[384+tid];
            g_part[(b*16 + pp)*320 + tid] = s;
        }

        const int cp = tid & 31, gp = tid >> 5;
        for (int m = 0; m < 4; m++) {
            const float* W1 = (m == 0) ? cW1 : fW1 + (size_t)(m-1)*Dx*Hx;
            const float* B1 = (m == 0) ? cb1 : fb1 + (m-1)*Hx;
            const float* W2 = (m == 0) ? cW2 : fW2 + (m-1)*Hx;
            float B2 = (m == 0) ? cb2[0] : fb2[m-1];
            __syncthreads();
            for (int i = tid; i < Dx*Hx/4; i += NT)
                ((float4*)sW1s)[i] = ((const float4*)W1)[i];
            if (tid < 64) sW2v[tid] = W2[tid];
            __syncthreads();
            {   // hidden: 2 cols x 2 nodes per thread, float4 over d
                const float4* A0 = (const float4*)(sX + gp*Dx);
                const float4* A1 = (const float4*)(sX + (gp+16)*Dx);
                float2 bc = *(const float2*)(B1 + 2*cp);
                float r00 = bc.x, r01 = bc.y, r10 = bc.x, r11 = bc.y;
                #pragma unroll 4
                for (int d4 = 0; d4 < Dx/4; d4++) {
                    float4 a0 = A0[d4], a1 = A1[d4];
                    const float* wd = sW1s + d4*256 + 2*cp;
                    float2 w0 = *(const float2*)(wd);
                    float2 w1 = *(const float2*)(wd + 64);
                    float2 w2 = *(const float2*)(wd + 128);
                    float2 w3 = *(const float2*)(wd + 192);
                    r00 += a0.x*w0.x + a0.y*w1.x + a0.z*w2.x + a0.w*w3.x;
                    r01 += a0.x*w0.y + a0.y*w1.y + a0.z*w2.y + a0.w*w3.y;
                    r10 += a1.x*w0.x + a1.y*w1.x + a1.z*w2.x + a1.w*w3.x;
                    r11 += a1.x*w0.y + a1.y*w1.y + a1.z*w2.y + a1.w*w3.y;
                }
                *(float2*)(sHid + gp*64 + 2*cp)      = make_float2(fmaxf(r00,0.f), fmaxf(r01,0.f));
                *(float2*)(sHid + (gp+16)*64 + 2*cp) = make_float2(fmaxf(r10,0.f), fmaxf(r11,0.f));
            }
            __syncthreads();
            // scalar head: warp per node, 2 rounds
            for (int nn = 0; nn < 2; nn++) {
                int nl = w*2 + nn;
                float v = sHid[nl*64 + lane] * sW2v[lane]
                        + sHid[nl*64 + 32 + lane] * sW2v[32 + lane];
                #pragma unroll
                for (int o = 16; o > 0; o >>= 1) v += __shfl_xor_sync(full, v, o);
                if (lane == 0) {
                    float sig = 1.f / (1.f + expf(-(v + B2)));
                    int node = nodeBase + nl;
                    if (m == 0) g_kap[node] = sig; else g_f[m-1][node] = sig;
                }
            }
        }
        if (bid == 0) {   // scalar m1 = sigmoid(MLP(1))
            float* s1 = sm + 15000;
            float* s2 = s1 + 64;
            __syncthreads();
            if (tid < 64) s1[tid] = fmaxf(wmW1[tid] + wmb1[tid], 0.f);
            __syncthreads();
            if (tid < 32) {
                float a = wmb2[tid];
                #pragma unroll
                for (int i = 0; i < 64; i++) a += s1[i] * wmW2[i*32 + tid];
                s2[tid] = fmaxf(a, 0.f);
            }
            __syncthreads();
            if (tid == 0) {
                float s = wmb3[0];
                #pragma unroll
                for (int i = 0; i < 32; i++) s += s2[i] * wmW3[i];
                g_m1 = 1.f / (1.f + expf(-s));
            }
        }
    }

    gridbar(0);   // kap/f/m1/adj ready

    // ================= PHASE 2: prune (blocks 0-7) + curv1 + gin0 =========
    if (bid < Bx) {   // prune batch b = bid; 1 element per thread
        int b = bid;
        float* sv = sm;         // 512
        float* so = sm + 512;   // 512
        float v = g_kap[b*Nx + tid];
        sv[tid] = v; so[tid] = v;
        __syncthreads();
        for (int k = 2; k <= Nx; k <<= 1)
            for (int j = k >> 1; j > 0; j >>= 1) {
                int ixj = tid ^ j;
                if (ixj > tid) {
                    float a = sv[tid], c = sv[ixj];
                    bool up = ((tid & k) == 0);
                    if ((a > c) == up) { sv[tid] = c; sv[ixj] = a; }
                }
                __syncthreads();
            }
        int p = *p_ptr;
        float keepA = 1.f, keepB = 1.f;
        for (int phase = 0; phase < 2; phase++) {
            int kk = (Nx * p * (phase+1)) / 100;
            bool removed = false;
            if (kk >= 1) {
                float T = sv[Nx - kk];
                int cgt = __syncthreads_count(so[tid] > T);
                int need = kk - cgt;
                removed = (so[tid] > T);
                bool eq = (so[tid] == T) && (need > 0);
                unsigned bal = __ballot_sync(full, eq);
                if (lane == 0) wcnt[w] = __popc(bal);
                __syncthreads();
                int off = 0;
                #pragma unroll
                for (int i = 0; i < 16; i++) if (i < w) off += wcnt[i];
                int rank = off + __popc(bal & ((1u << lane) - 1u));
                if (eq && rank < need) removed = true;
            }
            if (phase == 0) keepA = removed ? 0.f : 1.f;
            else           keepB = removed ? 0.f : 1.f;
            __syncthreads();
        }
        unsigned mA = __ballot_sync(full, keepA != 0.f);
        unsigned mB = __ballot_sync(full, keepA * keepB != 0.f);
        if (lane == 0) { g_kmask1[b*16 + w] = mA; g_kmask2[b*16 + w] = mB; }
        __syncthreads();
    }

    {   // curv pass 1: batch = bid>>4, 32 rows/block, 2 rows/warp
        int b2 = bid >> 4;
        int rowbase = (bid & 15) * 32;
        __syncthreads();
        for (int i = tid; i < FNx*Nx; i += NT)
            sm[i] = g_f[i >> 9][b2*Nx + (i & 511)];
        __syncthreads();
        float m1 = g_m1;
        unsigned myw[2];
        #pragma unroll
        for (int k = 0; k < 2; k++) {
            int row = rowbase + w*2 + k;
            myw[k] = (lane < 16) ? g_adj[(size_t)(b2*Nx + row)*16 + lane] : 0u;
        }
        int degi[2];
        #pragma unroll
        for (int k = 0; k < 2; k++) degi[k] = __popc(myw[k]);
        float u1[2][FNx], u2[2][FNx];
        #pragma unroll
        for (int k = 0; k < 2; k++)
            #pragma unroll
            for (int i = 0; i < FNx; i++) { u1[k][i] = 0.f; u2[k][i] = 0.f; }
        #pragma unroll
        for (int c = 0; c < 16; c++) {
            float fv[FNx];
            #pragma unroll
            for (int i = 0; i < FNx; i++) fv[i] = sm[i*512 + c*32 + lane];
            #pragma unroll
            for (int k = 0; k < 2; k++) {
                unsigned bits = __shfl_sync(full, myw[k], c);
                float sel = (float)((bits >> lane) & 1u);
                #pragma unroll
                for (int i = 0; i < FNx; i++) {
                    u1[k][i] += sel * fv[i];
                    u2[k][i] += sel * fv[i] * fv[i];
                }
            }
        }
        #pragma unroll
        for (int o = 16; o > 0; o >>= 1) {
            #pragma unroll
            for (int k = 0; k < 2; k++) {
                degi[k] += __shfl_xor_sync(full, degi[k], o);
                #pragma unroll
                for (int i = 0; i < FNx; i++) {
                    u1[k][i] += __shfl_xor_sync(full, u1[k][i], o);
                    u2[k][i] += __shfl_xor_sync(full, u2[k][i], o);
                }
            }
        }
        if (lane == 0) {
            #pragma unroll
            for (int k = 0; k < 2; k++) {
                int row = rowbase + w*2 + k;
                int idx = b2*Nx + row;
                float deg = (float)degi[k];
                g_deg[idx] = deg;
                #pragma unroll
                for (int i = 0; i < FNx; i++) {
                    float fr = sm[i*512 + row];
                    g_u1[i][idx] = u1[k][i];
                    float gam = 0.5f*m1*(fr*fr*deg - 2.f*fr*u1[k][i] + u2[k][i]);
                    float df  = m1*(fr*deg - u1[k][i]);
                    g_gamma[i][idx] = gam; g_df[i][idx] = df; g_fdf[i][idx] = fr*df;
                }
            }
        }
        __syncthreads();
    }

    {   // gin layer 0 (partials -> cols 128..191)
        float eps1 = 1.f + eps[0];
        gin_phase<128>(sm, X, nullptr, eps1, g0W1, g0b1, g0W2, g0b2, &g_h[0][0], 128);
    }

    gridbar(1);   // gamma/df/fdf, kmask1, h0 ready

    // ================= PHASE 3: curv2 + gin1 ==============================
    {   // curv pass 2
        int b2 = bid >> 4;
        int rowbase = (bid & 15) * 32;
        float* sgam = sm;            // 3*512
        float* sdf  = sm + 1536;
        float* sfd  = sm + 3072;
        for (int i = tid; i < FNx*Nx; i += NT) {
            int f = i >> 9, j = i & 511, id2 = b2*Nx + j;
            sgam[f*512 + j] = g_gamma[f][id2];
            sdf[f*512 + j]  = g_df[f][id2];
            sfd[f*512 + j]  = g_fdf[f][id2];
        }
        __syncthreads();
        float m1 = g_m1;
        unsigned myw[2];
        #pragma unroll
        for (int k = 0; k < 2; k++) {
            int row = rowbase + w*2 + k;
            myw[k] = (lane < 16) ? g_adj[(size_t)(b2*Nx + row)*16 + lane] : 0u;
        }
        float v1[2][FNx], v2[2][FNx], v3[2][FNx];
        #pragma unroll
        for (int k = 0; k < 2; k++)
            #pragma unroll
            for (int i = 0; i < FNx; i++) { v1[k][i]=0.f; v2[k][i]=0.f; v3[k][i]=0.f; }
        #pragma unroll
        for (int c = 0; c < 16; c++) {
            int j = c*32 + lane;
            float gv[FNx], dv[FNx], fv[FNx];
            #pragma unroll
            for (int i = 0; i < FNx; i++) {
                gv[i] = sgam[i*512 + j]; dv[i] = sdf[i*512 + j]; fv[i] = sfd[i*512 + j];
            }
            #pragma unroll
            for (int k = 0; k < 2; k++) {
                unsigned bits = __shfl_sync(full, myw[k], c);
                float sel = (float)((bits >> lane) & 1u);
                #pragma unroll
                for (int i = 0; i < FNx; i++) {
                    v1[k][i] += sel * gv[i];
                    v2[k][i] += sel * dv[i];
                    v3[k][i] += sel * fv[i];
                }
            }
        }
        #pragma unroll
        for (int o = 16; o > 0; o >>= 1) {
            #pragma unroll
            for (int k = 0; k < 2; k++)
                #pragma unroll
                for (int i = 0; i < FNx; i++) {
                    v1[k][i] += __shfl_xor_sync(full, v1[k][i], o);
                    v2[k][i] += __shfl_xor_sync(full, v2[k][i], o);
                    v3[k][i] += __shfl_xor_sync(full, v3[k][i], o);
                }
        }
        if (lane == 0) {
            #pragma unroll
            for (int k = 0; k < 2; k++) {
                int row = rowbase + w*2 + k;
                int idx = b2*Nx + row;
                float deg = g_deg[idx], kap = g_kap[idx];
                float term = 0.f;
                #pragma unroll
                for (int i = 0; i < FNx; i++) {
                    float gam = sgam[i*512 + row], df = sdf[i*512 + row], fdf = sfd[i*512 + row];
                    float fr = g_f[i][idx];
                    float u1v = g_u1[i][idx];
                    float dgam = m1*(gam*deg - v1[k][i]);
                    float gfd  = 0.5f*m1*(fdf*deg - fr*v2[k][i] - df*u1v + v3[k][i]);
                    float g2 = 0.5f*dgam - gfd;
                    term += fmaxf(kap*gam - g2, 0.f);
                }
                g_rowloss[idx] = term - 3.f*kap;
            }
        }
        __syncthreads();
    }
    {   // gin layer 1 (partials -> cols 192..255)
        float eps1 = 1.f + eps[1];
        gin_phase<64>(sm, &g_h[0][0], g_kmask1, eps1, g1W1, g1b1, g1W2, g1b2, &g_h[1][0], 192);
    }

    gridbar(2);   // h1, rowloss ready

    // ================= PHASE 4: gin2 (no h write) + loss reduce ===========
    {
        float eps1 = 1.f + eps[2];
        gin_phase<64>(sm, &g_h[1][0], g_kmask2, eps1, g2W1, g2b1, g2W2, g2b2, nullptr, 256);
    }
    if (bid == NB-1) {   // loss reduction (rowloss ready since gridbar(2))
        float lp = 0.f;
        #pragma unroll
        for (int i = tid; i < BN; i += NT) lp += g_rowloss[i];
        float* L = sm;
        L[tid] = lp;
        __syncthreads();
        for (int o = 256; o > 0; o >>= 1) { if (tid < o) L[tid] += L[tid + o]; __syncthreads(); }
        if (tid == 0) g_loss = L[0];
    }

    gridbar(3);   // all partials + loss ready

    // ================= PHASE 5: final output GEMM =========================
    if (bid < Bx) {
        int b = bid;
        float* S = sm;
        if (tid < 320) {
            float a = 0.f;
            #pragma unroll
            for (int p2 = 0; p2 < 16; p2++) a += g_part[(b*16 + p2)*320 + tid];
            S[tid] = a;
        }
        __syncthreads();
        if (w < OUTC) {   // warp per output column
            float acc = 0.f;
            for (int f = lane; f < 320; f += 32) acc += S[f] * outW[f*OUTC + w];
            #pragma unroll
            for (int o = 16; o > 0; o >>= 1) acc += __shfl_xor_sync(full, acc, o);
            if (lane == 0) dout[b*OUTC + w] = acc + outb[w];
        }
        if (b == 0 && tid == 320 && out_size > Bx*OUTC) dout[Bx*OUTC] = g_loss;
    }
}

// ---------------- launch ----------------
extern "C" void kernel_launch(void* const* d_in, const int* in_sizes, int n_in,
                              void* d_out, int out_size) {
    const float* X    = (const float*)d_in[0];
    const float* A    = (const float*)d_in[1];
    const int*   p    = (const int*)  d_in[2];
    const float* cW1  = (const float*)d_in[3];
    const float* cb1  = (const float*)d_in[4];
    const float* cW2  = (const float*)d_in[5];
    const float* cb2  = (const float*)d_in[6];
    const float* wmW1 = (const float*)d_in[7];
    const float* wmb1 = (const float*)d_in[8];
    const float* wmW2 = (const float*)d_in[9];
    const float* wmb2 = (const float*)d_in[10];
    const float* wmW3 = (const float*)d_in[11];
    const float* wmb3 = (const float*)d_in[12];
    const float* fW1  = (const float*)d_in[13];
    const float* fb1  = (const float*)d_in[14];
    const float* fW2  = (const float*)d_in[15];
    const float* fb2  = (const float*)d_in[16];
    const float* eps  = (const float*)d_in[17];
    const float* g0W1 = (const float*)d_in[18];
    const float* g0b1 = (const float*)d_in[19];
    const float* g0W2 = (const float*)d_in[20];
    const float* g0b2 = (const float*)d_in[21];
    const float* g1W1 = (const float*)d_in[22];
    const float* g1b1 = (const float*)d_in[23];
    const float* g1W2 = (const float*)d_in[24];
    const float* g1b2 = (const float*)d_in[25];
    const float* g2W1 = (const float*)d_in[26];
    const float* g2b1 = (const float*)d_in[27];
    const float* g2W2 = (const float*)d_in[28];
    const float* g2b2 = (const float*)d_in[29];
    const float* outW = (const float*)d_in[30];
    const float* outb = (const float*)d_in[31];
    float* dout = (float*)d_out;

    // dyn smem: max phase = gin<128>: 18448 floats ≈ 73792 B
    static const int SMEM = 73792;
    cudaFuncSetAttribute((const void*)mega_kernel,
        cudaFuncAttributeMaxDynamicSharedMemorySize, SMEM);

    mega_kernel<<<NB, NT, SMEM>>>(X, A, p,
        cW1, cb1, cW2, cb2,
        wmW1, wmb1, wmW2, wmb2, wmW3, wmb3,
        fW1, fb1, fW2, fb2, eps,
        g0W1, g0b1, g0W2, g0b2,
        g1W1, g1b1, g1W2, g1b2,
        g2W1, g2b1, g2W2, g2b2,
        outW, outb, dout, out_size);
}